// round 11
// baseline (speedup 1.0000x reference)
#include <cuda_runtime.h>
#include <cuda_fp16.h>
#include <cstdint>

#define NN 50000
#define EE 800000
#define FF 512
#define HH 128
#define CC 40
#define NCAT 640     // (1 + 4) * 128
#define NB_SCAN 196  // ceil(NN / 256)

// pair counts (k-pair packed half2 weights)
#define PIN   (256 * 128)     // input weights:  512x128 -> 256x128 pairs
#define PCH   (64 * 128)      // one chain layer: 128x128 -> 64x128 pairs
#define PMAIN (PIN + 10 * PCH)
#define POUT  (320 * 40)      // out weights: 640x40 -> 320x40 pairs

// ---------------- scratch (device globals; no allocation allowed) -----------
static __device__ __align__(256) float    g_deg[NN];
static __device__ __align__(256) __half   g_ah[NN * HH];   // aggr outputs
static __device__ __align__(256) __half   g_a2[NN * HH];
static __device__ __align__(256) __half   g_a3[NN * HH];
static __device__ __align__(256) __half   g_b1[NN * HH];   // gemm outputs
static __device__ __align__(256) __half   g_b2[NN * HH];
static __device__ __align__(256) __half   g_b3[NN * HH];
static __device__ __align__(256) __half   g_cat[(size_t)NN * NCAT];  // fp16 concat
// pre-packed split-fp16 weights: [k2][n] = half2(W[2k2][n], W[2k2+1][n])
static __device__ __align__(256) uint32_t g_wph[PMAIN], g_wpl[PMAIN];
static __device__ __align__(256) uint32_t g_woh[POUT],  g_wol[POUT];
// CSR scratch
static __device__ __align__(256) int   g_cnt[NN];
static __device__ __align__(256) int   g_rowptr[NN + 1];
static __device__ __align__(256) int   g_cursor[NN];
static __device__ __align__(256) int2  g_edge[EE];          // {src, w-as-int}
static __device__ __align__(256) int   g_bsum[256];
static __device__ __align__(256) int   g_boff[256];

__device__ __forceinline__ uint32_t pack2(float a, float b) {
    __half2 h = __floats2half2_rn(a, b);
    return *(uint32_t*)&h;
}

__device__ __forceinline__ void mma_f16(float c[4], uint32_t a0, uint32_t a1,
                                        uint32_t a2, uint32_t a3,
                                        uint32_t b0, uint32_t b1) {
    asm volatile(
        "mma.sync.aligned.m16n8k16.row.col.f32.f16.f16.f32 "
        "{%0,%1,%2,%3}, {%4,%5,%6,%7}, {%8,%9}, {%0,%1,%2,%3};"
        : "+f"(c[0]), "+f"(c[1]), "+f"(c[2]), "+f"(c[3])
        : "r"(a0), "r"(a1), "r"(a2), "r"(a3), "r"(b0), "r"(b1));
}

// ---------------- job batching structs ---------------------------------------
struct GJob {                    // one chain GEMM: dst = A @ Wk + bias
    const __half* A;  int lda;
    const uint32_t *Bh, *Bl;
    const float* bias;
    __half* dst;      int ldo;
};
struct GBatch { GJob j[4]; };

struct AJob {                    // one aggregation: out = A_norm * in
    const __half* in; int lda;
    __half* out;
};
struct ABatch { AJob j[3]; };

// ---------------- weight pre-split + k-pair pack ----------------------------
__global__ void k_wsplit(const float* __restrict__ W_in,
                         const float* __restrict__ W_gcn,
                         const float* __restrict__ W_out,
                         uint32_t* __restrict__ wph, uint32_t* __restrict__ wpl,
                         uint32_t* __restrict__ woh, uint32_t* __restrict__ wol) {
    int i = blockIdx.x * blockDim.x + threadIdx.x;
    float v0, v1;
    uint32_t *ph, *pl;
    int idx;
    if (i < PIN) {                      // input: [512][128]
        int k2 = i / 128, n = i % 128;
        v0 = W_in[(2 * k2) * 128 + n];
        v1 = W_in[(2 * k2 + 1) * 128 + n];
        ph = wph; pl = wpl; idx = i;
    } else if (i < PMAIN) {             // chains: 10 x [128][128]
        int j = i - PIN;
        int l = j / PCH, r = j % PCH;
        int k2 = r / 128, n = r % 128;
        v0 = W_gcn[l * HH * HH + (2 * k2) * 128 + n];
        v1 = W_gcn[l * HH * HH + (2 * k2 + 1) * 128 + n];
        ph = wph; pl = wpl; idx = i;
    } else if (i < PMAIN + POUT) {      // out: [640][40]
        int j = i - PMAIN;
        int k2 = j / 40, n = j % 40;
        v0 = W_out[(2 * k2) * 40 + n];
        v1 = W_out[(2 * k2 + 1) * 40 + n];
        ph = woh; pl = wol; idx = j;
    } else return;

    __half h0 = __float2half_rn(v0), h1 = __float2half_rn(v1);
    float l0 = v0 - __half2float(h0), l1 = v1 - __half2float(h1);
    __half2 hh = __halves2half2(h0, h1);
    ph[idx] = *(uint32_t*)&hh;
    pl[idx] = pack2(l0, l1);
}

// ---------------- degree / CSR build ----------------------------------------
__global__ void k_deg_init(float* __restrict__ deg, int* __restrict__ cnt) {
    int i = blockIdx.x * blockDim.x + threadIdx.x;
    if (i < NN) { deg[i] = 1.0f; cnt[i] = 0; }
}

__global__ void k_deg_acc(const int* __restrict__ ei, const float* __restrict__ ew,
                          float* __restrict__ deg, int* __restrict__ cnt) {
    int e = blockIdx.x * blockDim.x + threadIdx.x;
    if (e < EE) {
        int d = ei[EE + e];
        atomicAdd(&deg[d], ew[e]);
        atomicAdd(&cnt[d], 1);
    }
}

__global__ void k_scan1(const int* __restrict__ cnt, int* __restrict__ bsum) {
    __shared__ int s[256];
    int i = blockIdx.x * 256 + threadIdx.x;
    s[threadIdx.x] = (i < NN) ? cnt[i] : 0;
    __syncthreads();
    for (int off = 128; off > 0; off >>= 1) {
        if (threadIdx.x < off) s[threadIdx.x] += s[threadIdx.x + off];
        __syncthreads();
    }
    if (threadIdx.x == 0) bsum[blockIdx.x] = s[0];
}

__global__ void k_scan2(const int* __restrict__ bsum, int* __restrict__ boff,
                        int* __restrict__ rowptr) {
    __shared__ int s[256];
    int t = threadIdx.x;
    int v = (t < NB_SCAN) ? bsum[t] : 0;
    s[t] = v;
    __syncthreads();
    for (int off = 1; off < 256; off <<= 1) {
        int u = (t >= off) ? s[t - off] : 0;
        __syncthreads();
        s[t] += u;
        __syncthreads();
    }
    boff[t] = s[t] - v;
    if (t == 255) rowptr[NN] = s[255];
}

__global__ void k_scan3(const int* __restrict__ cnt, const int* __restrict__ boff,
                        int* __restrict__ rowptr, int* __restrict__ cursor) {
    __shared__ int s[256];
    int i = blockIdx.x * 256 + threadIdx.x;
    int t = threadIdx.x;
    int v = (i < NN) ? cnt[i] : 0;
    s[t] = v;
    __syncthreads();
    for (int off = 1; off < 256; off <<= 1) {
        int u = (t >= off) ? s[t - off] : 0;
        __syncthreads();
        s[t] += u;
        __syncthreads();
    }
    int ex = boff[blockIdx.x] + s[t] - v;
    if (i < NN) { rowptr[i] = ex; cursor[i] = ex; }
}

__global__ void k_fill(const int* __restrict__ ei, const float* __restrict__ ew,
                       const float* __restrict__ deg, int* __restrict__ cursor,
                       int2* __restrict__ edge) {
    int e = blockIdx.x * blockDim.x + threadIdx.x;
    if (e < EE) {
        int s = ei[e], d = ei[EE + e];
        int pos = atomicAdd(&cursor[d], 1);
        float w = ew[e] * rsqrtf(deg[s]) * rsqrtf(deg[d]);
        edge[pos] = make_int2(s, __float_as_int(w));
    }
}

#define LDP 136   // stride (u32) : conflict-free fragment loads

// ---------------- input GEMM: fp32 A split to fp16 hi/lo, 3-pass HMMA -------
__global__ __launch_bounds__(256) void k_mma_in(
    const float* __restrict__ A,
    const uint32_t* __restrict__ Bh_g, const uint32_t* __restrict__ Bl_g,
    const float* __restrict__ bias, __half* __restrict__ catH)
{
    __shared__ uint32_t Ah[8 * LDP], Al[8 * LDP];
    __shared__ uint32_t Bh[8 * LDP], Bl[8 * LDP];

    const int tid  = threadIdx.x;
    const int wid  = tid >> 5;
    const int lane = tid & 31;
    const int g    = lane >> 2;
    const int tg   = lane & 3;
    const int wm   = (wid & 3) * 32;
    const int wn   = (wid >> 2) * 64;
    const int brow = blockIdx.x * 128;

    int ar[2], ac[2];
#pragma unroll
    for (int l = 0; l < 2; l++) {
        int v = tid + l * 256;
        ar[l] = v >> 2;  ac[l] = (v & 3) * 4;
    }
    const int brr = tid >> 5;
    const int bcc = (tid & 31) * 4;

    float acc[2][8][4];
#pragma unroll
    for (int mt = 0; mt < 2; mt++)
#pragma unroll
        for (int nt = 0; nt < 8; nt++)
#pragma unroll
            for (int j = 0; j < 4; j++) acc[mt][nt][j] = 0.0f;

    const int nt_tiles = FF / 16;

    float4 pa[2];
    uint4  pbh, pbl;

    auto fetch = [&](int t) {
#pragma unroll
        for (int l = 0; l < 2; l++) {
            int grow = brow + ar[l];
            pa[l] = make_float4(0.f, 0.f, 0.f, 0.f);
            if (grow < NN)
                pa[l] = *(const float4*)&A[(size_t)grow * FF + t * 16 + ac[l]];
        }
        pbh = *(const uint4*)&Bh_g[(size_t)(t * 8 + brr) * 128 + bcc];
        pbl = *(const uint4*)&Bl_g[(size_t)(t * 8 + brr) * 128 + bcc];
    };
    auto store = [&]() {
#pragma unroll
        for (int l = 0; l < 2; l++) {
            float fx = pa[l].x, fy = pa[l].y, fz = pa[l].z, fw = pa[l].w;
            __half hx = __float2half_rn(fx), hy = __float2half_rn(fy);
            __half hz = __float2half_rn(fz), hw_ = __float2half_rn(fw);
            __half2 h01 = __halves2half2(hx, hy), h23 = __halves2half2(hz, hw_);
            int k2 = ac[l] >> 1;
            Ah[(k2 + 0) * LDP + ar[l]] = *(uint32_t*)&h01;
            Ah[(k2 + 1) * LDP + ar[l]] = *(uint32_t*)&h23;
            Al[(k2 + 0) * LDP + ar[l]] =
                pack2(fx - __half2float(hx), fy - __half2float(hy));
            Al[(k2 + 1) * LDP + ar[l]] =
                pack2(fz - __half2float(hz), fw - __half2float(hw_));
        }
        *(uint4*)&Bh[brr * LDP + bcc] = pbh;
        *(uint4*)&Bl[brr * LDP + bcc] = pbl;
    };

    fetch(0);
    store();
    __syncthreads();

    for (int t = 0; t < nt_tiles; t++) {
        if (t + 1 < nt_tiles) fetch(t + 1);

        uint32_t a0h[2], a1h[2], a2h[2], a3h[2];
        uint32_t a0l[2], a1l[2], a2l[2], a3l[2];
#pragma unroll
        for (int mt = 0; mt < 2; mt++) {
            int m0 = wm + mt * 16;
            a0h[mt] = Ah[tg * LDP + m0 + g];
            a1h[mt] = Ah[tg * LDP + m0 + g + 8];
            a2h[mt] = Ah[(tg + 4) * LDP + m0 + g];
            a3h[mt] = Ah[(tg + 4) * LDP + m0 + g + 8];
            a0l[mt] = Al[tg * LDP + m0 + g];
            a1l[mt] = Al[tg * LDP + m0 + g + 8];
            a2l[mt] = Al[(tg + 4) * LDP + m0 + g];
            a3l[mt] = Al[(tg + 4) * LDP + m0 + g + 8];
        }
#pragma unroll
        for (int nt = 0; nt < 8; nt++) {
            int n0 = wn + nt * 8;
            uint32_t b0h = Bh[tg * LDP + n0 + g];
            uint32_t b1h = Bh[(tg + 4) * LDP + n0 + g];
            uint32_t b0l = Bl[tg * LDP + n0 + g];
            uint32_t b1l = Bl[(tg + 4) * LDP + n0 + g];
#pragma unroll
            for (int mt = 0; mt < 2; mt++) {
                mma_f16(acc[mt][nt], a0h[mt], a1h[mt], a2h[mt], a3h[mt], b0h, b1h);
                mma_f16(acc[mt][nt], a0l[mt], a1l[mt], a2l[mt], a3l[mt], b0h, b1h);
                mma_f16(acc[mt][nt], a0h[mt], a1h[mt], a2h[mt], a3h[mt], b0l, b1l);
            }
        }
        if (t + 1 < nt_tiles) {
            __syncthreads();
            store();
            __syncthreads();
        }
    }

#pragma unroll
    for (int mt = 0; mt < 2; mt++) {
        int r0 = brow + wm + mt * 16 + g;
        int r1 = r0 + 8;
#pragma unroll
        for (int nt = 0; nt < 8; nt++) {
            int col = wn + nt * 8 + tg * 2;
            float b0 = bias[col], b1 = bias[col + 1];
            if (r0 < NN)
                *(__half2*)&catH[(size_t)r0 * NCAT + col] =
                    __floats2half2_rn(acc[mt][nt][0] + b0, acc[mt][nt][1] + b1);
            if (r1 < NN)
                *(__half2*)&catH[(size_t)r1 * NCAT + col] =
                    __floats2half2_rn(acc[mt][nt][2] + b0, acc[mt][nt][3] + b1);
        }
    }
}

// ---------------- batched chain GEMM: fp16 A (exact), 2-pass HMMA, +bias ----
// gridDim.y = job index; dst = A @ Wk + bias
__global__ __launch_bounds__(256) void k_mma_hb(GBatch batch)
{
    const GJob jb = batch.j[blockIdx.y];

    __shared__ uint32_t As[8 * LDP];
    __shared__ uint32_t Bh[8 * LDP], Bl[8 * LDP];

    const int tid  = threadIdx.x;
    const int wid  = tid >> 5;
    const int lane = tid & 31;
    const int g    = lane >> 2;
    const int tg   = lane & 3;
    const int wm   = (wid & 3) * 32;
    const int wn   = (wid >> 2) * 64;
    const int brow = blockIdx.x * 128;

    const int ar  = tid >> 1;
    const int ak2 = (tid & 1) * 4;
    const int brr = tid >> 5;
    const int bcc = (tid & 31) * 4;

    float acc[2][8][4];
#pragma unroll
    for (int mt = 0; mt < 2; mt++)
#pragma unroll
        for (int nt = 0; nt < 8; nt++)
#pragma unroll
            for (int j = 0; j < 4; j++) acc[mt][nt][j] = 0.0f;

    const int nt_tiles = HH / 16;

    uint4 pa, pbh, pbl;

    auto fetch = [&](int t) {
        int grow = brow + ar;
        pa = make_uint4(0, 0, 0, 0);
        if (grow < NN)
            pa = *(const uint4*)&jb.A[(size_t)grow * jb.lda + t * 16 + ak2 * 2];
        pbh = *(const uint4*)&jb.Bh[(size_t)(t * 8 + brr) * 128 + bcc];
        pbl = *(const uint4*)&jb.Bl[(size_t)(t * 8 + brr) * 128 + bcc];
    };
    auto store = [&]() {
        const uint32_t* hp = (const uint32_t*)&pa;
#pragma unroll
        for (int j = 0; j < 4; j++)
            As[(ak2 + j) * LDP + ar] = hp[j];
        *(uint4*)&Bh[brr * LDP + bcc] = pbh;
        *(uint4*)&Bl[brr * LDP + bcc] = pbl;
    };

    fetch(0);
    store();
    __syncthreads();

    for (int t = 0; t < nt_tiles; t++) {
        if (t + 1 < nt_tiles) fetch(t + 1);

        uint32_t a0[2], a1[2], a2[2], a3[2];
#pragma unroll
        for (int mt = 0; mt < 2; mt++) {
            int m0 = wm + mt * 16;
            a0[mt] = As[tg * LDP + m0 + g];
            a1[mt] = As[tg * LDP + m0 + g + 8];
            a2[mt] = As[(tg + 4) * LDP + m0 + g];
            a3[mt] = As[(tg + 4) * LDP + m0 + g + 8];
        }
#pragma unroll
        for (int nt = 0; nt < 8; nt++) {
            int n0 = wn + nt * 8;
            uint32_t b0h = Bh[tg * LDP + n0 + g];
            uint32_t b1h = Bh[(tg + 4) * LDP + n0 + g];
            uint32_t b0l = Bl[tg * LDP + n0 + g];
            uint32_t b1l = Bl[(tg + 4) * LDP + n0 + g];
#pragma unroll
            for (int mt = 0; mt < 2; mt++) {
                mma_f16(acc[mt][nt], a0[mt], a1[mt], a2[mt], a3[mt], b0h, b1h);
                mma_f16(acc[mt][nt], a0[mt], a1[mt], a2[mt], a3[mt], b0l, b1l);
            }
        }
        if (t + 1 < nt_tiles) {
            __syncthreads();
            store();
            __syncthreads();
        }
    }

#pragma unroll
    for (int mt = 0; mt < 2; mt++) {
        int r0 = brow + wm + mt * 16 + g;
        int r1 = r0 + 8;
#pragma unroll
        for (int nt = 0; nt < 8; nt++) {
            int col = wn + nt * 8 + tg * 2;
            float b0 = jb.bias[col], b1 = jb.bias[col + 1];
            if (r0 < NN)
                *(__half2*)&jb.dst[(size_t)r0 * jb.ldo + col] =
                    __floats2half2_rn(acc[mt][nt][0] + b0, acc[mt][nt][1] + b1);
            if (r1 < NN)
                *(__half2*)&jb.dst[(size_t)r1 * jb.ldo + col] =
                    __floats2half2_rn(acc[mt][nt][2] + b0, acc[mt][nt][3] + b1);
        }
    }
}

// ---------------- batched CSR aggregation: out = A_norm * in ----------------
__global__ __launch_bounds__(256) void k_aggrb(
    const int* __restrict__ rowptr, const int2* __restrict__ edge,
    const float* __restrict__ deg, ABatch batch)
{
    const AJob jb = batch.j[blockIdx.y];

    int node = (blockIdx.x * blockDim.x + threadIdx.x) >> 5;
    if (node >= NN) return;
    int lane = threadIdx.x & 31;

    const uint2* mh = (const uint2*)jb.in;
    const int ld2 = jb.lda >> 2;

    auto loadf4 = [&](int n) -> float4 {
        uint2 p = __ldg(&mh[(size_t)n * ld2 + lane]);
        __half2 h0 = *(__half2*)&p.x;
        __half2 h1 = *(__half2*)&p.y;
        float2 f0 = __half22float2(h0);
        float2 f1 = __half22float2(h1);
        return make_float4(f0.x, f0.y, f1.x, f1.y);
    };

    float sn = 1.0f / deg[node];
    float4 self = loadf4(node);
    float4 acc;
    acc.x = self.x * sn;
    acc.y = self.y * sn;
    acc.z = self.z * sn;
    acc.w = self.w * sn;

    int e  = rowptr[node];
    int e1 = rowptr[node + 1];
    for (; e + 3 < e1; e += 4) {
        int2 p0 = __ldg(&edge[e]),     p1 = __ldg(&edge[e + 1]);
        int2 p2 = __ldg(&edge[e + 2]), p3 = __ldg(&edge[e + 3]);
        float w0 = __int_as_float(p0.y), w1 = __int_as_float(p1.y);
        float w2 = __int_as_float(p2.y), w3 = __int_as_float(p3.y);
        float4 v0 = loadf4(p0.x), v1 = loadf4(p1.x);
        float4 v2 = loadf4(p2.x), v3 = loadf4(p3.x);
        acc.x += w0 * v0.x + w1 * v1.x + w2 * v2.x + w3 * v3.x;
        acc.y += w0 * v0.y + w1 * v1.y + w2 * v2.y + w3 * v3.y;
        acc.z += w0 * v0.z + w1 * v1.z + w2 * v2.z + w3 * v3.z;
        acc.w += w0 * v0.w + w1 * v1.w + w2 * v2.w + w3 * v3.w;
    }
    for (; e < e1; e++) {
        int2 p0 = __ldg(&edge[e]);
        float w0 = __int_as_float(p0.y);
        float4 v0 = loadf4(p0.x);
        acc.x += w0 * v0.x;
        acc.y += w0 * v0.y;
        acc.z += w0 * v0.z;
        acc.w += w0 * v0.w;
    }

    union { uint2 u; __half2 h[2]; } pk;
    pk.h[0] = __floats2half2_rn(acc.x, acc.y);
    pk.h[1] = __floats2half2_rn(acc.z, acc.w);
    *(uint2*)&jb.out[(size_t)node * HH + lane * 4] = pk.u;
}

// ---------------- final: out = cat16 @ W_out + b_out (2-pass HMMA) ----------
#define LDA2 264

__global__ __launch_bounds__(256) void k_out(
    const __half* __restrict__ cat,
    const uint32_t* __restrict__ Woh, const uint32_t* __restrict__ Wol,
    const float* __restrict__ b, float* __restrict__ out)
{
    __shared__ uint32_t As[8 * LDA2];
    __shared__ uint32_t Bh[8 * 40], Bl[8 * 40];

    const int tid  = threadIdx.x;
    const int wid  = tid >> 5;
    const int lane = tid & 31;
    const int g    = lane >> 2;
    const int tg   = lane & 3;
    const int wm   = wid * 32;
    const int brow = blockIdx.x * 256;

    float acc[2][5][4];
#pragma unroll
    for (int mt = 0; mt < 2; mt++)
#pragma unroll
        for (int nt = 0; nt < 5; nt++)
#pragma unroll
            for (int j = 0; j < 4; j++) acc[mt][nt][j] = 0.0f;

    for (int t = 0; t < NCAT / 16; t++) {
#pragma unroll
        for (int l = 0; l < 2; l++) {
            int v   = tid + l * 256;
            int r   = v >> 1;
            int k2  = (v & 1) * 4;
            int grow = brow + r;
            uint4 av = make_uint4(0, 0, 0, 0);
            if (grow < NN)
                av = *(const uint4*)&cat[(size_t)grow * NCAT + t * 16 + k2 * 2];
            const uint32_t* hp = (const uint32_t*)&av;
#pragma unroll
            for (int j = 0; j < 4; j++)
                As[(k2 + j) * LDA2 + r] = hp[j];
        }
        for (int idx = tid; idx < 8 * 40; idx += 256) {
            Bh[idx] = Woh[t * 320 + idx];
            Bl[idx] = Wol[t * 320 + idx];
        }
        __syncthreads();

        uint32_t a0[2], a1[2], a2[2], a3[2];
#pragma unroll
        for (int mt = 0; mt < 2; mt++) {
            int m0 = wm + mt * 16;
            a0[mt] = As[tg * LDA2 + m0 + g];
            a1[mt] = As[tg * LDA2 + m0 + g + 8];
            a2[mt] = As[(tg + 4) * LDA2 + m0 + g];
            a3[mt] = As[(tg + 4) * LDA2 + m0 + g + 8];
        }
#pragma unroll
        for (int nt = 0; nt < 5; nt++) {
            int n0 = nt * 8;
            uint32_t b0h = Bh[tg * 40 + n0 + g];
            uint32_t b1h = Bh[(tg + 4) * 40 + n0 + g];
            uint32_t b0l = Bl[tg * 40 + n0 + g];
            uint32_t b1l = Bl[(tg + 4) * 40 + n0 + g];
#pragma unroll
            for (int mt = 0; mt < 2; mt++) {
                mma_f16(acc[mt][nt], a0[mt], a1[mt], a2[mt], a3[mt], b0h, b1h);
                mma_f16(acc[mt][nt], a0[mt], a1[mt], a2[mt], a3[mt], b0l, b1l);
            }
        }
        __syncthreads();
    }

#pragma unroll
    for (int mt = 0; mt < 2; mt++) {
        int r0 = brow + wm + mt * 16 + g;
        int r1 = r0 + 8;
#pragma unroll
        for (int nt = 0; nt < 5; nt++) {
            int col = nt * 8 + tg * 2;
            float b0 = b[col], b1 = b[col + 1];
            if (r0 < NN) {
                float2 v = make_float2(acc[mt][nt][0] + b0, acc[mt][nt][1] + b1);
                *(float2*)&out[(size_t)r0 * CC + col] = v;
            }
            if (r1 < NN) {
                float2 v = make_float2(acc[mt][nt][2] + b0, acc[mt][nt][3] + b1);
                *(float2*)&out[(size_t)r1 * CC + col] = v;
            }
        }
    }
}

// ---------------- launch (single stream, level-batched) ----------------------
extern "C" void kernel_launch(void* const* d_in, const int* in_sizes, int n_in,
                              void* d_out, int out_size) {
    const float* x     = (const float*)d_in[0];
    const int*   ei    = (const int*)  d_in[1];
    const float* ew    = (const float*)d_in[2];
    const float* W_in  = (const float*)d_in[3];
    const float* b_in  = (const float*)d_in[4];
    const float* W_gcn = (const float*)d_in[5];
    const float* b_gcn = (const float*)d_in[6];
    const float* W_out = (const float*)d_in[7];
    const float* b_out = (const float*)d_in[8];
    float* out = (float*)d_out;

    float* deg;
    __half *ah, *a2, *a3, *b1, *b2, *b3, *cat;
    uint32_t *wph, *wpl, *woh, *wol;
    int *cnt, *rowptr, *cursor, *bsum, *boff;
    int2* edge;
    cudaGetSymbolAddress((void**)&deg,    g_deg);
    cudaGetSymbolAddress((void**)&ah,     g_ah);
    cudaGetSymbolAddress((void**)&a2,     g_a2);
    cudaGetSymbolAddress((void**)&a3,     g_a3);
    cudaGetSymbolAddress((void**)&b1,     g_b1);
    cudaGetSymbolAddress((void**)&b2,     g_b2);
    cudaGetSymbolAddress((void**)&b3,     g_b3);
    cudaGetSymbolAddress((void**)&cat,    g_cat);
    cudaGetSymbolAddress((void**)&wph,    g_wph);
    cudaGetSymbolAddress((void**)&wpl,    g_wpl);
    cudaGetSymbolAddress((void**)&woh,    g_woh);
    cudaGetSymbolAddress((void**)&wol,    g_wol);
    cudaGetSymbolAddress((void**)&cnt,    g_cnt);
    cudaGetSymbolAddress((void**)&rowptr, g_rowptr);
    cudaGetSymbolAddress((void**)&cursor, g_cursor);
    cudaGetSymbolAddress((void**)&edge,   g_edge);
    cudaGetSymbolAddress((void**)&bsum,   g_bsum);
    cudaGetSymbolAddress((void**)&boff,   g_boff);

    const int gb = (NN + 127) / 128;
    const int ga = (NN * 32 + 255) / 256;

    k_wsplit  <<<(PMAIN + POUT + 255) / 256, 256>>>(W_in, W_gcn, W_out,
                                                    wph, wpl, woh, wol);
    k_deg_init<<<(NN + 255) / 256, 256>>>(deg, cnt);
    k_deg_acc <<<(EE + 255) / 256, 256>>>(ei, ew, deg, cnt);
    k_scan1   <<<NB_SCAN, 256>>>(cnt, bsum);
    k_scan2   <<<1, 256>>>(bsum, boff, rowptr);
    k_mma_in  <<<gb, 256>>>(x, wph, wpl, b_in, cat);      // h -> cat[:,0:128]
    k_scan3   <<<NB_SCAN, 256>>>(cnt, boff, rowptr, cursor);
    k_fill    <<<(EE + 255) / 256, 256>>>(ei, ew, deg, cursor, edge);

    auto gjob = [&](const __half* A, int lda, int k, __half* dst, int ldo) {
        GJob j;
        j.A = A; j.lda = lda;
        j.Bh = wph + PIN + (size_t)k * PCH;
        j.Bl = wpl + PIN + (size_t)k * PCH;
        j.bias = b_gcn + (size_t)k * HH;
        j.dst = dst; j.ldo = ldo;
        return j;
    };
    auto ajob = [&](const __half* in, int lda, __half* o) {
        AJob j; j.in = in; j.lda = lda; j.out = o; return j;
    };
    auto run_g = [&](GBatch gbat, int n) {
        k_mma_hb<<<dim3(gb, n), 256>>>(gbat);
    };
    auto run_a = [&](ABatch abat, int n) {
        k_aggrb<<<dim3(ga / 1, n), 256>>>(rowptr, edge, deg, abat);
    };

    const __half* h = cat;                       // stride NCAT

    // Level 1: ah = A*h ; 4 GEMMs from ah
    { ABatch ab; ab.j[0] = ajob(h, NCAT, ah); run_a(ab, 1); }
    { GBatch gbat;
      gbat.j[0] = gjob(ah, HH, 0, cat + 1 * HH, NCAT);   // chain 1 done
      gbat.j[1] = gjob(ah, HH, 1, b1, HH);               // chain 2 L1
      gbat.j[2] = gjob(ah, HH, 3, b2, HH);               // chain 3 L1
      gbat.j[3] = gjob(ah, HH, 6, b3, HH);               // chain 4 L1
      run_g(gbat, 4); }

    // Level 2
    { ABatch ab;
      ab.j[0] = ajob(b1, HH, ah);
      ab.j[1] = ajob(b2, HH, a2);
      ab.j[2] = ajob(b3, HH, a3);
      run_a(ab, 3); }
    { GBatch gbat;
      gbat.j[0] = gjob(ah, HH, 2, cat + 2 * HH, NCAT);   // chain 2 done
      gbat.j[1] = gjob(a2, HH, 4, b2, HH);               // chain 3 L2
      gbat.j[2] = gjob(a3, HH, 7, b3, HH);               // chain 4 L2
      run_g(gbat, 3); }

    // Level 3
    { ABatch ab;
      ab.j[0] = ajob(b2, HH, a2);
      ab.j[1] = ajob(b3, HH, a3);
      run_a(ab, 2); }
    { GBatch gbat;
      gbat.j[0] = gjob(a2, HH, 5, cat + 3 * HH, NCAT);   // chain 3 done
      gbat.j[1] = gjob(a3, HH, 8, b3, HH);               // chain 4 L3
      run_g(gbat, 2); }

    // Level 4
    { ABatch ab; ab.j[0] = ajob(b3, HH, a3); run_a(ab, 1); }
    { GBatch gbat;
      gbat.j[0] = gjob(a3, HH, 9, cat + 4 * HH, NCAT);   // chain 4 done
      run_g(gbat, 1); }

    // out = cat @ W_out + b_out
    k_out<<<(NN + 255) / 256, 256>>>(cat, woh, wol, b_out, out);
}

// round 12
// speedup vs baseline: 1.2349x; 1.2349x over previous
#include <cuda_runtime.h>
#include <cuda_fp16.h>
#include <cstdint>

#define NN 50000
#define EE 800000
#define FF 512
#define HH 128
#define CC 40
#define NCAT 640     // (1 + 4) * 128
#define NB_SCAN 196  // ceil(NN / 256)

#define PIN   (256 * 128)     // input weights:  512x128 -> 256x128 pairs
#define POUT  (320 * 40)      // out weights: 640x40 -> 320x40 pairs
#define PC    8192            // one chain product: 64x128 pairs

// ---------------- scratch (device globals; no allocation allowed) -----------
static __device__ __align__(256) float    g_deg[NN];
static __device__ __align__(256) __half   g_ah1[NN * HH];  // A^1 h .. A^4 h
static __device__ __align__(256) __half   g_ah2[NN * HH];
static __device__ __align__(256) __half   g_ah3[NN * HH];
static __device__ __align__(256) __half   g_ah4[NN * HH];
static __device__ __align__(256) __half   g_cat[(size_t)NN * NCAT];
// split-fp16 packed weights
static __device__ __align__(256) uint32_t g_wph[PIN],  g_wpl[PIN];    // input
static __device__ __align__(256) uint32_t g_woh[POUT], g_wol[POUT];   // out
static __device__ __align__(256) uint32_t g_wch[4 * PC], g_wcl[4 * PC]; // chain prods
// fp32 weight-product scratch: 0:S2 1:S45 2:S345 3:S89 4:S789 5:S6789
static __device__ __align__(256) float    g_S[6 * 16384];
static __device__ __align__(256) float    g_C[16 * 128];   // corrections [chain][t][n]
static __device__ __align__(256) float    g_R[NN * 4];     // (1, r1, r2, r3) per node
// CSR scratch
static __device__ __align__(256) int   g_cnt[NN];
static __device__ __align__(256) int   g_rowptr[NN + 1];
static __device__ __align__(256) int   g_cursor[NN];
static __device__ __align__(256) int2  g_edge[EE];         // {src, w-as-int}
static __device__ __align__(256) int   g_bsum[256];
static __device__ __align__(256) int   g_boff[256];

__device__ __forceinline__ uint32_t pack2(float a, float b) {
    __half2 h = __floats2half2_rn(a, b);
    return *(uint32_t*)&h;
}

__device__ __forceinline__ void mma_f16(float c[4], uint32_t a0, uint32_t a1,
                                        uint32_t a2, uint32_t a3,
                                        uint32_t b0, uint32_t b1) {
    asm volatile(
        "mma.sync.aligned.m16n8k16.row.col.f32.f16.f16.f32 "
        "{%0,%1,%2,%3}, {%4,%5,%6,%7}, {%8,%9}, {%0,%1,%2,%3};"
        : "+f"(c[0]), "+f"(c[1]), "+f"(c[2]), "+f"(c[3])
        : "r"(a0), "r"(a1), "r"(a2), "r"(a3), "r"(b0), "r"(b1));
}

// ---------------- weight pre-split (input + output weights) -----------------
__global__ void k_wsplit(const float* __restrict__ W_in,
                         const float* __restrict__ W_out,
                         uint32_t* __restrict__ wph, uint32_t* __restrict__ wpl,
                         uint32_t* __restrict__ woh, uint32_t* __restrict__ wol) {
    int i = blockIdx.x * blockDim.x + threadIdx.x;
    float v0, v1;
    uint32_t *ph, *pl;
    int idx;
    if (i < PIN) {
        int k2 = i / 128, n = i % 128;
        v0 = W_in[(2 * k2) * 128 + n];
        v1 = W_in[(2 * k2 + 1) * 128 + n];
        ph = wph; pl = wpl; idx = i;
    } else if (i < PIN + POUT) {
        int j = i - PIN;
        int k2 = j / 40, n = j % 40;
        v0 = W_out[(2 * k2) * 40 + n];
        v1 = W_out[(2 * k2 + 1) * 40 + n];
        ph = woh; pl = wol; idx = j;
    } else return;
    __half h0 = __float2half_rn(v0), h1 = __float2half_rn(v1);
    float l0 = v0 - __half2float(h0), l1 = v1 - __half2float(h1);
    __half2 hh = __halves2half2(h0, h1);
    ph[idx] = *(uint32_t*)&hh;
    pl[idx] = pack2(l0, l1);
}

#define LDP 136

// ---------------- one-block fp32 128x128x128 product via 3-pass HMMA --------
struct PJob { const float* A; const float* B; float* O; };
struct PBatch { PJob j[3]; };

__global__ __launch_bounds__(256) void k_prod(PBatch batch)
{
    const PJob jb = batch.j[blockIdx.y];

    __shared__ uint32_t Ah[8 * LDP], Al[8 * LDP];
    __shared__ uint32_t Bh[8 * LDP], Bl[8 * LDP];

    const int tid  = threadIdx.x;
    const int wid  = tid >> 5;
    const int lane = tid & 31;
    const int g    = lane >> 2;
    const int tg   = lane & 3;
    const int wm   = (wid & 3) * 32;
    const int wn   = (wid >> 2) * 64;

    int ar[2], ac[2];
#pragma unroll
    for (int l = 0; l < 2; l++) {
        int v = tid + l * 256;
        ar[l] = v >> 2;  ac[l] = (v & 3) * 4;
    }
    const int bk2 = tid >> 5;          // 0..7
    const int bn4 = (tid & 31) * 4;

    float acc[2][8][4];
#pragma unroll
    for (int mt = 0; mt < 2; mt++)
#pragma unroll
        for (int nt = 0; nt < 8; nt++)
#pragma unroll
            for (int j = 0; j < 4; j++) acc[mt][nt][j] = 0.0f;

    for (int t = 0; t < 8; t++) {
        // A tile 128x16 fp32 -> split pairs [k2][m]
#pragma unroll
        for (int l = 0; l < 2; l++) {
            float4 av = *(const float4*)&jb.A[(size_t)ar[l] * 128 + t * 16 + ac[l]];
            float aa[4] = {av.x, av.y, av.z, av.w};
            int k2 = ac[l] >> 1;
            __half h0 = __float2half_rn(aa[0]), h1 = __float2half_rn(aa[1]);
            __half h2 = __float2half_rn(aa[2]), h3 = __float2half_rn(aa[3]);
            __half2 p01 = __halves2half2(h0, h1), p23 = __halves2half2(h2, h3);
            Ah[(k2 + 0) * LDP + ar[l]] = *(uint32_t*)&p01;
            Ah[(k2 + 1) * LDP + ar[l]] = *(uint32_t*)&p23;
            Al[(k2 + 0) * LDP + ar[l]] =
                pack2(aa[0] - __half2float(h0), aa[1] - __half2float(h1));
            Al[(k2 + 1) * LDP + ar[l]] =
                pack2(aa[2] - __half2float(h2), aa[3] - __half2float(h3));
        }
        // B tile 16x128 fp32 -> split pairs [k2][n]
        {
            const float* r0 = &jb.B[(size_t)(t * 16 + 2 * bk2) * 128 + bn4];
            const float* r1 = r0 + 128;
            float4 bv0 = *(const float4*)r0;
            float4 bv1 = *(const float4*)r1;
            float e0[4] = {bv0.x, bv0.y, bv0.z, bv0.w};
            float e1[4] = {bv1.x, bv1.y, bv1.z, bv1.w};
#pragma unroll
            for (int j = 0; j < 4; j++) {
                __half h0 = __float2half_rn(e0[j]), h1 = __float2half_rn(e1[j]);
                __half2 hp = __halves2half2(h0, h1);
                Bh[bk2 * LDP + bn4 + j] = *(uint32_t*)&hp;
                Bl[bk2 * LDP + bn4 + j] =
                    pack2(e0[j] - __half2float(h0), e1[j] - __half2float(h1));
            }
        }
        __syncthreads();

        uint32_t a0h[2], a1h[2], a2h[2], a3h[2];
        uint32_t a0l[2], a1l[2], a2l[2], a3l[2];
#pragma unroll
        for (int mt = 0; mt < 2; mt++) {
            int m0 = wm + mt * 16;
            a0h[mt] = Ah[tg * LDP + m0 + g];
            a1h[mt] = Ah[tg * LDP + m0 + g + 8];
            a2h[mt] = Ah[(tg + 4) * LDP + m0 + g];
            a3h[mt] = Ah[(tg + 4) * LDP + m0 + g + 8];
            a0l[mt] = Al[tg * LDP + m0 + g];
            a1l[mt] = Al[tg * LDP + m0 + g + 8];
            a2l[mt] = Al[(tg + 4) * LDP + m0 + g];
            a3l[mt] = Al[(tg + 4) * LDP + m0 + g + 8];
        }
#pragma unroll
        for (int nt = 0; nt < 8; nt++) {
            int n0 = wn + nt * 8;
            uint32_t b0h = Bh[tg * LDP + n0 + g];
            uint32_t b1h = Bh[(tg + 4) * LDP + n0 + g];
            uint32_t b0l = Bl[tg * LDP + n0 + g];
            uint32_t b1l = Bl[(tg + 4) * LDP + n0 + g];
#pragma unroll
            for (int mt = 0; mt < 2; mt++) {
                mma_f16(acc[mt][nt], a0h[mt], a1h[mt], a2h[mt], a3h[mt], b0h, b1h);
                mma_f16(acc[mt][nt], a0l[mt], a1l[mt], a2l[mt], a3l[mt], b0h, b1h);
                mma_f16(acc[mt][nt], a0h[mt], a1h[mt], a2h[mt], a3h[mt], b0l, b1l);
            }
        }
        __syncthreads();
    }

#pragma unroll
    for (int mt = 0; mt < 2; mt++) {
        int r0 = wm + mt * 16 + g;
        int r1 = r0 + 8;
#pragma unroll
        for (int nt = 0; nt < 8; nt++) {
            int col = wn + nt * 8 + tg * 2;
            *(float2*)&jb.O[(size_t)r0 * 128 + col] =
                make_float2(acc[mt][nt][0], acc[mt][nt][1]);
            *(float2*)&jb.O[(size_t)r1 * 128 + col] =
                make_float2(acc[mt][nt][2], acc[mt][nt][3]);
        }
    }
}

// ---------------- pack chain-product weights to split-fp16 pairs ------------
__global__ void k_pack(const float* __restrict__ W_gcn,
                       const float* __restrict__ S,
                       uint32_t* __restrict__ wch, uint32_t* __restrict__ wcl) {
    int i = blockIdx.x * blockDim.x + threadIdx.x;
    if (i >= 4 * PC) return;
    int c = i / PC, p = i % PC;
    int k2 = p / 128, n = p % 128;
    const float* M;
    switch (c) {
        case 0: M = W_gcn;          break;   // chain 1: W0
        case 1: M = S + 0 * 16384;  break;   // chain 2: S2
        case 2: M = S + 2 * 16384;  break;   // chain 3: S345
        default: M = S + 5 * 16384; break;   // chain 4: S6789
    }
    float v0 = M[(2 * k2) * 128 + n];
    float v1 = M[(2 * k2 + 1) * 128 + n];
    __half h0 = __float2half_rn(v0), h1 = __float2half_rn(v1);
    __half2 hh = __halves2half2(h0, h1);
    wch[i] = *(uint32_t*)&hh;
    wcl[i] = pack2(v0 - __half2float(h0), v1 - __half2float(h1));
}

// ---------------- correction vectors: C[chain][t][n] ------------------------
// 16 blocks (c = b>>2, t = b&3), 128 threads each.
__global__ void k_cvec(const float* __restrict__ b_gcn,
                       const float* __restrict__ S,
                       float* __restrict__ C) {
    int blk = blockIdx.x;
    int c = blk >> 2, t = blk & 3;
    int n = threadIdx.x;
    if (n >= 128) return;

    const float* bias = nullptr;   // bias vector (128)
    const float* mat  = nullptr;   // right multiplier (128x128) or null=identity
    int zero = 0;

    if (c == 0)      { if (t == 0) bias = b_gcn + 0 * HH; else zero = 1; }
    else if (c == 1) {
        if (t == 0)      bias = b_gcn + 2 * HH;
        else if (t == 1) { bias = b_gcn + 1 * HH; mat = nullptr; /*W2*/ }
        else zero = 1;
    }
    else if (c == 2) {
        if (t == 0)      bias = b_gcn + 5 * HH;
        else if (t == 1) bias = b_gcn + 4 * HH;          // * W5
        else if (t == 2) { bias = b_gcn + 3 * HH; mat = S + 1 * 16384; } // * S45
        else zero = 1;
    }
    else {
        if (t == 0)      bias = b_gcn + 9 * HH;
        else if (t == 1) bias = b_gcn + 8 * HH;          // * W9
        else if (t == 2) { bias = b_gcn + 7 * HH; mat = S + 3 * 16384; } // * S89
        else             { bias = b_gcn + 6 * HH; mat = S + 4 * 16384; } // * S789
    }

    float v = 0.0f;
    if (!zero) {
        // W-gcn direct multipliers for (1,1)->W2 and (2,1)->W5 and (3,1)->W9
        extern __shared__ float dummy[];   // unused
        const float* wdir = nullptr;
        if (c == 1 && t == 1) wdir = nullptr;   // set below via gW
        if (mat == nullptr && t > 0) {
            // right-multiply by a raw W_gcn matrix
            int widx = (c == 1) ? 2 : (c == 2 ? 5 : 9);
            // b^T * W_gcn[widx]
            const float* W = bias;     // placeholder to silence warnings
            (void)W;
            float s = 0.0f;
            const float* Wm = nullptr;
            // W_gcn base passed via b_gcn? No — pass separately: use gWg pointer below.
            // (handled by caller passing W_gcn via S-3 slot trick is ugly; instead:)
            Wm = (const float*)nullptr;
            (void)Wm; (void)widx; (void)s;
            v = 0.0f;   // overwritten below
        }
        if (t == 0) {
            v = bias[n];
        }
    }
    C[(c * 4 + t) * 128 + n] = v;
}

// NOTE: k_cvec above handles only t==0 and zero slots; matrix-multiplied
// corrections are computed in k_cvec2 (needs W_gcn + S).
__global__ void k_cvec2(const float* __restrict__ W_gcn,
                        const float* __restrict__ b_gcn,
                        const float* __restrict__ S,
                        float* __restrict__ C) {
    // 6 jobs x 128 cols
    int job = blockIdx.x;
    int n = threadIdx.x;
    if (n >= 128) return;
    const float* bias;
    const float* M;
    int slot;
    switch (job) {
        case 0: bias = b_gcn + 1 * HH; M = W_gcn + 2 * HH * HH; slot = 1 * 4 + 1; break; // b1*W2
        case 1: bias = b_gcn + 4 * HH; M = W_gcn + 5 * HH * HH; slot = 2 * 4 + 1; break; // b4*W5
        case 2: bias = b_gcn + 3 * HH; M = S + 1 * 16384;       slot = 2 * 4 + 2; break; // b3*S45
        case 3: bias = b_gcn + 8 * HH; M = W_gcn + 9 * HH * HH; slot = 3 * 4 + 1; break; // b8*W9
        case 4: bias = b_gcn + 7 * HH; M = S + 3 * 16384;       slot = 3 * 4 + 2; break; // b7*S89
        default: bias = b_gcn + 6 * HH; M = S + 4 * 16384;      slot = 3 * 4 + 3; break; // b6*S789
    }
    float s = 0.0f;
#pragma unroll 8
    for (int k = 0; k < 128; k++) s += bias[k] * M[k * 128 + n];
    C[slot * 128 + n] = s;
}

// ---------------- degree / CSR build ----------------------------------------
__global__ void k_deg_init(float* __restrict__ deg, int* __restrict__ cnt,
                           float* __restrict__ R) {
    int i = blockIdx.x * blockDim.x + threadIdx.x;
    if (i < NN) { deg[i] = 1.0f; cnt[i] = 0; R[i * 4] = 1.0f; }
}

__global__ void k_deg_acc(const int* __restrict__ ei, const float* __restrict__ ew,
                          float* __restrict__ deg, int* __restrict__ cnt) {
    int e = blockIdx.x * blockDim.x + threadIdx.x;
    if (e < EE) {
        int d = ei[EE + e];
        atomicAdd(&deg[d], ew[e]);
        atomicAdd(&cnt[d], 1);
    }
}

__global__ void k_scan1(const int* __restrict__ cnt, int* __restrict__ bsum) {
    __shared__ int s[256];
    int i = blockIdx.x * 256 + threadIdx.x;
    s[threadIdx.x] = (i < NN) ? cnt[i] : 0;
    __syncthreads();
    for (int off = 128; off > 0; off >>= 1) {
        if (threadIdx.x < off) s[threadIdx.x] += s[threadIdx.x + off];
        __syncthreads();
    }
    if (threadIdx.x == 0) bsum[blockIdx.x] = s[0];
}

__global__ void k_scan2(const int* __restrict__ bsum, int* __restrict__ boff,
                        int* __restrict__ rowptr) {
    __shared__ int s[256];
    int t = threadIdx.x;
    int v = (t < NB_SCAN) ? bsum[t] : 0;
    s[t] = v;
    __syncthreads();
    for (int off = 1; off < 256; off <<= 1) {
        int u = (t >= off) ? s[t - off] : 0;
        __syncthreads();
        s[t] += u;
        __syncthreads();
    }
    boff[t] = s[t] - v;
    if (t == 255) rowptr[NN] = s[255];
}

__global__ void k_scan3(const int* __restrict__ cnt, const int* __restrict__ boff,
                        int* __restrict__ rowptr, int* __restrict__ cursor) {
    __shared__ int s[256];
    int i = blockIdx.x * 256 + threadIdx.x;
    int t = threadIdx.x;
    int v = (i < NN) ? cnt[i] : 0;
    s[t] = v;
    __syncthreads();
    for (int off = 1; off < 256; off <<= 1) {
        int u = (t >= off) ? s[t - off] : 0;
        __syncthreads();
        s[t] += u;
        __syncthreads();
    }
    int ex = boff[blockIdx.x] + s[t] - v;
    if (i < NN) { rowptr[i] = ex; cursor[i] = ex; }
}

__global__ void k_fill(const int* __restrict__ ei, const float* __restrict__ ew,
                       const float* __restrict__ deg, int* __restrict__ cursor,
                       int2* __restrict__ edge) {
    int e = blockIdx.x * blockDim.x + threadIdx.x;
    if (e < EE) {
        int s = ei[e], d = ei[EE + e];
        int pos = atomicAdd(&cursor[d], 1);
        float w = ew[e] * rsqrtf(deg[s]) * rsqrtf(deg[d]);
        edge[pos] = make_int2(s, __float_as_int(w));
    }
}

// ---------------- r vectors: R[:,t] = A_norm * R[:,t-1] ---------------------
__global__ void k_rvec(const int* __restrict__ rowptr, const int2* __restrict__ edge,
                       const float* __restrict__ deg, float* __restrict__ R, int t) {
    int d = blockIdx.x * blockDim.x + threadIdx.x;
    if (d >= NN) return;
    float acc = R[d * 4 + t - 1] / deg[d];
    int e  = rowptr[d];
    int e1 = rowptr[d + 1];
    for (; e < e1; e++) {
        int2 p = __ldg(&edge[e]);
        acc += __int_as_float(p.y) * R[p.x * 4 + t - 1];
    }
    R[d * 4 + t] = acc;
}

// ---------------- input GEMM: fp32 A split to fp16 hi/lo, 3-pass HMMA -------
__global__ __launch_bounds__(256) void k_mma_in(
    const float* __restrict__ A,
    const uint32_t* __restrict__ Bh_g, const uint32_t* __restrict__ Bl_g,
    const float* __restrict__ bias, __half* __restrict__ catH)
{
    __shared__ uint32_t Ah[8 * LDP], Al[8 * LDP];
    __shared__ uint32_t Bh[8 * LDP], Bl[8 * LDP];

    const int tid  = threadIdx.x;
    const int wid  = tid >> 5;
    const int lane = tid & 31;
    const int g    = lane >> 2;
    const int tg   = lane & 3;
    const int wm   = (wid & 3) * 32;
    const int wn   = (wid >> 2) * 64;
    const int brow = blockIdx.x * 128;

    int ar[2], ac[2];
#pragma unroll
    for (int l = 0; l < 2; l++) {
        int v = tid + l * 256;
        ar[l] = v >> 2;  ac[l] = (v & 3) * 4;
    }
    const int brr = tid >> 5;
    const int bcc = (tid & 31) * 4;

    float acc[2][8][4];
#pragma unroll
    for (int mt = 0; mt < 2; mt++)
#pragma unroll
        for (int nt = 0; nt < 8; nt++)
#pragma unroll
            for (int j = 0; j < 4; j++) acc[mt][nt][j] = 0.0f;

    const int nt_tiles = FF / 16;

    float4 pa[2];
    uint4  pbh, pbl;

    auto fetch = [&](int t) {
#pragma unroll
        for (int l = 0; l < 2; l++) {
            int grow = brow + ar[l];
            pa[l] = make_float4(0.f, 0.f, 0.f, 0.f);
            if (grow < NN)
                pa[l] = *(const float4*)&A[(size_t)grow * FF + t * 16 + ac[l]];
        }
        pbh = *(const uint4*)&Bh_g[(size_t)(t * 8 + brr) * 128 + bcc];
        pbl = *(const uint4*)&Bl_g[(size_t)(t * 8 + brr) * 128 + bcc];
    };
    auto store = [&]() {
#pragma unroll
        for (int l = 0; l < 2; l++) {
            float fx = pa[l].x, fy = pa[l].y, fz = pa[l].z, fw = pa[l].w;
            __half hx = __float2half_rn(fx), hy = __float2half_rn(fy);
            __half hz = __float2half_rn(fz), hw_ = __float2half_rn(fw);
            __half2 h01 = __halves2half2(hx, hy), h23 = __halves2half2(hz, hw_);
            int k2 = ac[l] >> 1;
            Ah[(k2 + 0) * LDP + ar[l]] = *(uint32_t*)&h01;
            Ah[(k2 + 1) * LDP + ar[l]] = *(uint32_t*)&h23;
            Al[(k2 + 0) * LDP + ar[l]] =
                pack2(fx - __half2float(hx), fy - __half2float(hy));
            Al[(k2 + 1) * LDP + ar[l]] =
                pack2(fz - __half2float(hz), fw - __half2float(hw_));
        }
        *(uint4*)&Bh[brr * LDP + bcc] = pbh;
        *(uint4*)&Bl[brr * LDP + bcc] = pbl;
    };

    fetch(0);
    store();
    __syncthreads();

    for (int t = 0; t < nt_tiles; t++) {
        if (t + 1 < nt_tiles) fetch(t + 1);

        uint32_t a0h[2], a1h[2], a2h[2], a3h[2];
        uint32_t a0l[2], a1l[2], a2l[2], a3l[2];
#pragma unroll
        for (int mt = 0; mt < 2; mt++) {
            int m0 = wm + mt * 16;
            a0h[mt] = Ah[tg * LDP + m0 + g];
            a1h[mt] = Ah[tg * LDP + m0 + g + 8];
            a2h[mt] = Ah[(tg + 4) * LDP + m0 + g];
            a3h[mt] = Ah[(tg + 4) * LDP + m0 + g + 8];
            a0l[mt] = Al[tg * LDP + m0 + g];
            a1l[mt] = Al[tg * LDP + m0 + g + 8];
            a2l[mt] = Al[(tg + 4) * LDP + m0 + g];
            a3l[mt] = Al[(tg + 4) * LDP + m0 + g + 8];
        }
#pragma unroll
        for (int nt = 0; nt < 8; nt++) {
            int n0 = wn + nt * 8;
            uint32_t b0h = Bh[tg * LDP + n0 + g];
            uint32_t b1h = Bh[(tg + 4) * LDP + n0 + g];
            uint32_t b0l = Bl[tg * LDP + n0 + g];
            uint32_t b1l = Bl[(tg + 4) * LDP + n0 + g];
#pragma unroll
            for (int mt = 0; mt < 2; mt++) {
                mma_f16(acc[mt][nt], a0h[mt], a1h[mt], a2h[mt], a3h[mt], b0h, b1h);
                mma_f16(acc[mt][nt], a0l[mt], a1l[mt], a2l[mt], a3l[mt], b0h, b1h);
                mma_f16(acc[mt][nt], a0h[mt], a1h[mt], a2h[mt], a3h[mt], b0l, b1l);
            }
        }
        if (t + 1 < nt_tiles) {
            __syncthreads();
            store();
            __syncthreads();
        }
    }

#pragma unroll
    for (int mt = 0; mt < 2; mt++) {
        int r0 = brow + wm + mt * 16 + g;
        int r1 = r0 + 8;
#pragma unroll
        for (int nt = 0; nt < 8; nt++) {
            int col = wn + nt * 8 + tg * 2;
            float b0 = bias[col], b1 = bias[col + 1];
            if (r0 < NN)
                *(__half2*)&catH[(size_t)r0 * NCAT + col] =
                    __floats2half2_rn(acc[mt][nt][0] + b0, acc[mt][nt][1] + b1);
            if (r1 < NN)
                *(__half2*)&catH[(size_t)r1 * NCAT + col] =
                    __floats2half2_rn(acc[mt][nt][2] + b0, acc[mt][nt][3] + b1);
        }
    }
}

// ---------------- chain GEMM with rank-1 correction epilogue ----------------
// dst = A @ Wc + sum_t R[row][t] * C[t][col]
__global__ __launch_bounds__(256) void k_mma_c(
    const __half* __restrict__ A,
    const uint32_t* __restrict__ Bh_g, const uint32_t* __restrict__ Bl_g,
    const float* __restrict__ Cc, const float* __restrict__ R4,
    __half* __restrict__ dst, int ldo)
{
    __shared__ uint32_t As[8 * LDP];
    __shared__ uint32_t Bh[8 * LDP], Bl[8 * LDP];
    __shared__ float Cs[4][128];

    const int tid  = threadIdx.x;
    const int wid  = tid >> 5;
    const int lane = tid & 31;
    const int g    = lane >> 2;
    const int tg   = lane & 3;
    const int wm   = (wid & 3) * 32;
    const int wn   = (wid >> 2) * 64;
    const int brow = blockIdx.x * 128;

    // load corrections
    Cs[tid >> 7][(tid & 127)] = Cc[tid];                    // t = 0,1
    Cs[2 + (tid >> 7)][(tid & 127)] = Cc[256 + tid];        // t = 2,3

    const int ar  = tid >> 1;
    const int ak2 = (tid & 1) * 4;
    const int brr = tid >> 5;
    const int bcc = (tid & 31) * 4;

    float acc[2][8][4];
#pragma unroll
    for (int mt = 0; mt < 2; mt++)
#pragma unroll
        for (int nt = 0; nt < 8; nt++)
#pragma unroll
            for (int j = 0; j < 4; j++) acc[mt][nt][j] = 0.0f;

    uint4 pa, pbh, pbl;

    auto fetch = [&](int t) {
        int grow = brow + ar;
        pa = make_uint4(0, 0, 0, 0);
        if (grow < NN)
            pa = *(const uint4*)&A[(size_t)grow * HH + t * 16 + ak2 * 2];
        pbh = *(const uint4*)&Bh_g[(size_t)(t * 8 + brr) * 128 + bcc];
        pbl = *(const uint4*)&Bl_g[(size_t)(t * 8 + brr) * 128 + bcc];
    };
    auto store = [&]() {
        const uint32_t* hp = (const uint32_t*)&pa;
#pragma unroll
        for (int j = 0; j < 4; j++)
            As[(ak2 + j) * LDP + ar] = hp[j];
        *(uint4*)&Bh[brr * LDP + bcc] = pbh;
        *(uint4*)&Bl[brr * LDP + bcc] = pbl;
    };

    fetch(0);
    store();
    __syncthreads();

    for (int t = 0; t < 8; t++) {
        if (t + 1 < 8) fetch(t + 1);

        uint32_t a0[2], a1[2], a2[2], a3[2];
#pragma unroll
        for (int mt = 0; mt < 2; mt++) {
            int m0 = wm + mt * 16;
            a0[mt] = As[tg * LDP + m0 + g];
            a1[mt] = As[tg * LDP + m0 + g + 8];
            a2[mt] = As[(tg + 4) * LDP + m0 + g];
            a3[mt] = As[(tg + 4) * LDP + m0 + g + 8];
        }
#pragma unroll
        for (int nt = 0; nt < 8; nt++) {
            int n0 = wn + nt * 8;
            uint32_t b0h = Bh[tg * LDP + n0 + g];
            uint32_t b1h = Bh[(tg + 4) * LDP + n0 + g];
            uint32_t b0l = Bl[tg * LDP + n0 + g];
            uint32_t b1l = Bl[(tg + 4) * LDP + n0 + g];
#pragma unroll
            for (int mt = 0; mt < 2; mt++) {
                mma_f16(acc[mt][nt], a0[mt], a1[mt], a2[mt], a3[mt], b0h, b1h);
                mma_f16(acc[mt][nt], a0[mt], a1[mt], a2[mt], a3[mt], b0l, b1l);
            }
        }
        if (t + 1 < 8) {
            __syncthreads();
            store();
            __syncthreads();
        }
    }

#pragma unroll
    for (int mt = 0; mt < 2; mt++) {
        int r0 = brow + wm + mt * 16 + g;
        int r1 = r0 + 8;
        float4 rv0 = make_float4(0.f, 0.f, 0.f, 0.f);
        float4 rv1 = rv0;
        if (r0 < NN) rv0 = *(const float4*)&R4[(size_t)r0 * 4];
        if (r1 < NN) rv1 = *(const float4*)&R4[(size_t)r1 * 4];
#pragma unroll
        for (int nt = 0; nt < 8; nt++) {
            int col = wn + nt * 8 + tg * 2;
            float c00 = Cs[0][col],     c10 = Cs[1][col];
            float c20 = Cs[2][col],     c30 = Cs[3][col];
            float c01 = Cs[0][col + 1], c11 = Cs[1][col + 1];
            float c21 = Cs[2][col + 1], c31 = Cs[3][col + 1];
            if (r0 < NN) {
                float e0 = rv0.x * c00 + rv0.y * c10 + rv0.z * c20 + rv0.w * c30;
                float e1 = rv0.x * c01 + rv0.y * c11 + rv0.z * c21 + rv0.w * c31;
                *(__half2*)&dst[(size_t)r0 * ldo + col] =
                    __floats2half2_rn(acc[mt][nt][0] + e0, acc[mt][nt][1] + e1);
            }
            if (r1 < NN) {
                float e0 = rv1.x * c00 + rv1.y * c10 + rv1.z * c20 + rv1.w * c30;
                float e1 = rv1.x * c01 + rv1.y * c11 + rv1.z * c21 + rv1.w * c31;
                *(__half2*)&dst[(size_t)r1 * ldo + col] =
                    __floats2half2_rn(acc[mt][nt][2] + e0, acc[mt][nt][3] + e1);
            }
        }
    }
}

// ---------------- CSR aggregation: out = A_norm * in (fp16) -----------------
__global__ __launch_bounds__(256) void k_aggr(
    const int* __restrict__ rowptr, const int2* __restrict__ edge,
    const float* __restrict__ deg, const __half* __restrict__ Hin, int lda,
    __half* __restrict__ out)
{
    int node = (blockIdx.x * blockDim.x + threadIdx.x) >> 5;
    if (node >= NN) return;
    int lane = threadIdx.x & 31;

    const uint2* mh = (const uint2*)Hin;
    const int ld2 = lda >> 2;

    auto loadf4 = [&](int n) -> float4 {
        uint2 p = __ldg(&mh[(size_t)n * ld2 + lane]);
        __half2 h0 = *(__half2*)&p.x;
        __half2 h1 = *(__half2*)&p.y;
        float2 f0 = __half22float2(h0);
        float2 f1 = __half22float2(h1);
        return make_float4(f0.x, f0.y, f1.x, f1.y);
    };

    float sn = 1.0f / deg[node];
    float4 self = loadf4(node);
    float4 acc;
    acc.x = self.x * sn;
    acc.y = self.y * sn;
    acc.z = self.z * sn;
    acc.w = self.w * sn;

    int e  = rowptr[node];
    int e1 = rowptr[node + 1];
    for (; e + 3 < e1; e += 4) {
        int2 p0 = __ldg(&edge[e]),     p1 = __ldg(&edge[e + 1]);
        int2 p2 = __ldg(&edge[e + 2]), p3 = __ldg(&edge[e + 3]);
        float w0 = __int_as_float(p0.y), w1 = __int_as_float(p1.y);
        float w2 = __int_as_float(p2.y), w3 = __int_as_float(p3.y);
        float4 v0 = loadf4(p0.x), v1 = loadf4(p1.x);
        float4 v2 = loadf4(p2.x), v3 = loadf4(p3.x);
        acc.x += w0 * v0.x + w1 * v1.x + w2 * v2.x + w3 * v3.x;
        acc.y += w0 * v0.y + w1 * v1.y + w2 * v2.y + w3 * v3.y;
        acc.z += w0 * v0.z + w1 * v1.z + w2 * v2.z + w3 * v3.z;
        acc.w += w0 * v0.w + w1 * v1.w + w2 * v2.w + w3 * v3.w;
    }
    for (; e < e1; e++) {
        int2 p0 = __ldg(&edge[e]);
        float w0 = __int_as_float(p0.y);
        float4 v0 = loadf4(p0.x);
        acc.x += w0 * v0.x;
        acc.y += w0 * v0.y;
        acc.z += w0 * v0.z;
        acc.w += w0 * v0.w;
    }

    union { uint2 u; __half2 h[2]; } pk;
    pk.h[0] = __floats2half2_rn(acc.x, acc.y);
    pk.h[1] = __floats2half2_rn(acc.z, acc.w);
    *(uint2*)&out[(size_t)node * HH + lane * 4] = pk.u;
}

// ---------------- final: out = cat16 @ W_out + b_out (2-pass HMMA) ----------
#define LDA2 264

__global__ __launch_bounds__(256) void k_out(
    const __half* __restrict__ cat,
    const uint32_t* __restrict__ Woh, const uint32_t* __restrict__ Wol,
    const float* __restrict__ b, float* __restrict__ out)
{
    __shared__ uint32_t As[8 * LDA2];
    __shared__ uint32_t Bh[8 * 40], Bl[8 * 40];

    const int tid  = threadIdx.x;
    const int wid  = tid >> 5;
    const int lane = tid & 31;
    const int g    = lane >> 2;
    const int tg   = lane & 3;
    const int wm   = wid * 32;
    const int brow = blockIdx.x * 256;

    float acc[2][5][4];
#pragma unroll
    for (int mt = 0; mt < 2; mt++)
#pragma unroll
        for (int nt = 0; nt < 5; nt++)
#pragma unroll
            for (int j = 0; j < 4; j++) acc[mt][nt][j] = 0.0f;

    for (int t = 0; t < NCAT / 16; t++) {
#pragma unroll
        for (int l = 0; l < 2; l++) {
            int v   = tid + l * 256;
            int r   = v >> 1;
            int k2  = (v & 1) * 4;
            int grow = brow + r;
            uint4 av = make_uint4(0, 0, 0, 0);
            if (grow < NN)
                av = *(const uint4*)&cat[(size_t)grow * NCAT + t * 16 + k2 * 2];
            const uint32_t* hp = (const uint32_t*)&av;
#pragma unroll
            for (int j = 0; j < 4; j++)
                As[(k2 + j) * LDA2 + r] = hp[j];
        }
        for (int idx = tid; idx < 8 * 40; idx += 256) {
            Bh[idx] = Woh[t * 320 + idx];
            Bl[idx] = Wol[t * 320 + idx];
        }
        __syncthreads();

        uint32_t a0[2], a1[2], a2[2], a3[2];
#pragma unroll
        for (int mt = 0; mt < 2; mt++) {
            int m0 = wm + mt * 16;
            a0[mt] = As[tg * LDA2 + m0 + g];
            a1[mt] = As[tg * LDA2 + m0 + g + 8];
            a2[mt] = As[(tg + 4) * LDA2 + m0 + g];
            a3[mt] = As[(tg + 4) * LDA2 + m0 + g + 8];
        }
#pragma unroll
        for (int nt = 0; nt < 5; nt++) {
            int n0 = nt * 8;
            uint32_t b0h = Bh[tg * 40 + n0 + g];
            uint32_t b1h = Bh[(tg + 4) * 40 + n0 + g];
            uint32_t b0l = Bl[tg * 40 + n0 + g];
            uint32_t b1l = Bl[(tg + 4) * 40 + n0 + g];
#pragma unroll
            for (int mt = 0; mt < 2; mt++) {
                mma_f16(acc[mt][nt], a0[mt], a1[mt], a2[mt], a3[mt], b0h, b1h);
                mma_f16(acc[mt][nt], a0[mt], a1[mt], a2[mt], a3[mt], b0l, b1l);
            }
        }
        __syncthreads();
    }

#pragma unroll
    for (int mt = 0; mt < 2; mt++) {
        int r0 = brow + wm + mt * 16 + g;
        int r1 = r0 + 8;
#pragma unroll
        for (int nt = 0; nt < 5; nt++) {
            int col = nt * 8 + tg * 2;
            float b0 = b[col], b1 = b[col + 1];
            if (r0 < NN) {
                float2 v = make_float2(acc[mt][nt][0] + b0, acc[mt][nt][1] + b1);
                *(float2*)&out[(size_t)r0 * CC + col] = v;
            }
            if (r1 < NN) {
                float2 v = make_float2(acc[mt][nt][2] + b0, acc[mt][nt][3] + b1);
                *(float2*)&out[(size_t)r1 * CC + col] = v;
            }
        }
    }
}

// ---------------- launch (single stream) -------------------------------------
extern "C" void kernel_launch(void* const* d_in, const int* in_sizes, int n_in,
                              void* d_out, int out_size) {
    const float* x     = (const float*)d_in[0];
    const int*   ei    = (const int*)  d_in[1];
    const float* ew    = (const float*)d_in[2];
    const float* W_in  = (const float*)d_in[3];
    const float* b_in  = (const float*)d_in[4];
    const float* W_gcn = (const float*)d_in[5];
    const float* b_gcn = (const float*)d_in[6];
    const float* W_out = (const float*)d_in[7];
    const float* b_out = (const float*)d_in[8];
    float* out = (float*)d_out;

    float *deg, *S, *C, *R;
    __half *ah1, *ah2, *ah3, *ah4, *cat;
    uint32_t *wph, *wpl, *woh, *wol, *wch, *wcl;
    int *cnt, *rowptr, *cursor, *bsum, *boff;
    int2* edge;
    cudaGetSymbolAddress((void**)&deg,    g_deg);
    cudaGetSymbolAddress((void**)&ah1,    g_ah1);
    cudaGetSymbolAddress((void**)&ah2,    g_ah2);
    cudaGetSymbolAddress((void**)&ah3,    g_ah3);
    cudaGetSymbolAddress((void**)&ah4,    g_ah4);
    cudaGetSymbolAddress((void**)&cat,    g_cat);
    cudaGetSymbolAddress((void**)&wph,    g_wph);
    cudaGetSymbolAddress((void**)&wpl,    g_wpl);
    cudaGetSymbolAddress((void**)&woh,    g_woh);
    cudaGetSymbolAddress((void**)&wol,    g_wol);
    cudaGetSymbolAddress((void**)&wch,    g_wch);
    cudaGetSymbolAddress((void**)&wcl,    g_wcl);
    cudaGetSymbolAddress((void**)&S,      g_S);
    cudaGetSymbolAddress((void**)&C,      g_C);
    cudaGetSymbolAddress((void**)&R,      g_R);
    cudaGetSymbolAddress((void**)&cnt,    g_cnt);
    cudaGetSymbolAddress((void**)&rowptr, g_rowptr);
    cudaGetSymbolAddress((void**)&cursor, g_cursor);
    cudaGetSymbolAddress((void**)&edge,   g_edge);
    cudaGetSymbolAddress((void**)&bsum,   g_bsum);
    cudaGetSymbolAddress((void**)&boff,   g_boff);

    const int gb = (NN + 127) / 128;
    const int ga = (NN * 32 + 255) / 256;
    const float* Wg = W_gcn;

    // weights: split input/out, build chain products + corrections
    k_wsplit<<<(PIN + POUT + 255) / 256, 256>>>(W_in, W_out, wph, wpl, woh, wol);
    {   // step 1: S2 = W1*W2 ; S45 = W4*W5 ; S89 = W8*W9
        PBatch pb;
        pb.j[0] = {Wg + 1 * 16384, Wg + 2 * 16384, S + 0 * 16384};
        pb.j[1] = {Wg + 4 * 16384, Wg + 5 * 16384, S + 1 * 16384};
        pb.j[2] = {Wg + 8 * 16384, Wg + 9 * 16384, S + 3 * 16384};
        k_prod<<<dim3(1, 3), 256>>>(pb);
    }
    {   // step 2: S345 = W3*S45 ; S789 = W7*S89
        PBatch pb;
        pb.j[0] = {Wg + 3 * 16384, S + 1 * 16384, S + 2 * 16384};
        pb.j[1] = {Wg + 7 * 16384, S + 3 * 16384, S + 4 * 16384};
        pb.j[2] = pb.j[0];
        k_prod<<<dim3(1, 2), 256>>>(pb);
    }
    {   // step 3: S6789 = W6*S789
        PBatch pb;
        pb.j[0] = {Wg + 6 * 16384, S + 4 * 16384, S + 5 * 16384};
        pb.j[1] = pb.j[0]; pb.j[2] = pb.j[0];
        k_prod<<<dim3(1, 1), 256>>>(pb);
    }
    k_pack <<<(4 * PC + 255) / 256, 256>>>(Wg, S, wch, wcl);
    k_cvec <<<16, 128>>>(b_gcn, S, C);          // t==0 copies + zeros
    k_cvec2<<<6, 128>>>(Wg, b_gcn, S, C);       // matrix-multiplied terms

    // CSR + degree + r-vectors
    k_deg_init<<<(NN + 255) / 256, 256>>>(deg, cnt, R);
    k_deg_acc <<<(EE + 255) / 256, 256>>>(ei, ew, deg, cnt);
    k_scan1   <<<NB_SCAN, 256>>>(cnt, bsum);
    k_scan2   <<<1, 256>>>(bsum, boff, rowptr);
    k_mma_in  <<<gb, 256>>>(x, wph, wpl, b_in, cat);      // h -> cat[:,0:128]
    k_scan3   <<<NB_SCAN, 256>>>(cnt, boff, rowptr, cursor);
    k_fill    <<<(EE + 255) / 256, 256>>>(ei, ew, deg, cursor, edge);
    k_rvec    <<<NB_SCAN, 256>>>(rowptr, edge, deg, R, 1);
    k_rvec    <<<NB_SCAN, 256>>>(rowptr, edge, deg, R, 2);
    k_rvec    <<<NB_SCAN, 256>>>(rowptr, edge, deg, R, 3);

    // power sequence + chain GEMMs (interleaved for L2 locality)
    k_aggr <<<ga, 256>>>(rowptr, edge, deg, cat, NCAT, ah1);
    k_mma_c<<<gb, 256>>>(ah1, wch + 0 * PC, wcl + 0 * PC, C + 0 * 512, R,
                         cat + 1 * HH, NCAT);
    k_aggr <<<ga, 256>>>(rowptr, edge, deg, ah1, HH, ah2);
    k_mma_c<<<gb, 256>>>(ah2, wch + 1 * PC, wcl + 1 * PC, C + 1 * 512, R,
                         cat + 2 * HH, NCAT);
    k_aggr <<<ga, 256>>>(rowptr, edge, deg, ah2, HH, ah3);
    k_mma_c<<<gb, 256>>>(ah3, wch + 2 * PC, wcl + 2 * PC, C + 2 * 512, R,
                         cat + 3 * HH, NCAT);
    k_aggr <<<ga, 256>>>(rowptr, edge, deg, ah3, HH, ah4);
    k_mma_c<<<gb, 256>>>(ah4, wch + 3 * PC, wcl + 3 * PC, C + 3 * 512, R,
                         cat + 4 * HH, NCAT);

    // out = cat @ W_out + b_out
    k_out<<<(NN + 255) / 256, 256>>>(cat, woh, wol, b_out, out);
}

// round 13
// speedup vs baseline: 1.4198x; 1.1497x over previous
#include <cuda_runtime.h>
#include <cuda_fp16.h>
#include <cstdint>

#define NN 50000
#define EE 800000
#define FF 512
#define HH 128
#define CC 40
#define NCAT 640     // (1 + 4) * 128
#define NB_SCAN 196  // ceil(NN / 256)

#define PIN   (256 * 128)     // input weights:  512x128 -> 256x128 pairs
#define POUT  (320 * 40)      // out weights: 640x40 -> 320x40 pairs
#define PC    8192            // one chain product: 64x128 pairs

// ---------------- scratch (device globals; no allocation allowed) -----------
static __device__ __align__(256) float    g_deg[NN];
static __device__ __align__(256) __half   g_ah1[NN * HH];  // A^1 h .. A^4 h
static __device__ __align__(256) __half   g_ah2[NN * HH];
static __device__ __align__(256) __half   g_ah3[NN * HH];
static __device__ __align__(256) __half   g_ah4[NN * HH];
static __device__ __align__(256) __half   g_cat[(size_t)NN * NCAT];
// split-fp16 packed weights
static __device__ __align__(256) uint32_t g_wph[PIN],  g_wpl[PIN];    // input
static __device__ __align__(256) uint32_t g_woh[POUT], g_wol[POUT];   // out
static __device__ __align__(256) uint32_t g_wch[4 * PC], g_wcl[4 * PC]; // chain prods
// fp32 weight-product scratch: 0:S2 1:S45 2:S345 3:S89 4:S789 5:S6789
static __device__ __align__(256) float    g_S[6 * 16384];
static __device__ __align__(256) float    g_C[16 * 128];   // corrections [chain][t][n]
static __device__ __align__(256) float    g_R[NN * 4];     // (1, r1, r2, r3) per node
// CSR scratch
static __device__ __align__(256) int   g_cnt[NN];
static __device__ __align__(256) int   g_rowptr[NN + 1];
static __device__ __align__(256) int   g_cursor[NN];
static __device__ __align__(256) int2  g_edge[EE];         // {src, w-as-int}
static __device__ __align__(256) int   g_bsum[256];
static __device__ __align__(256) int   g_boff[256];

__device__ __forceinline__ uint32_t pack2(float a, float b) {
    __half2 h = __floats2half2_rn(a, b);
    return *(uint32_t*)&h;
}

__device__ __forceinline__ void mma_f16(float c[4], uint32_t a0, uint32_t a1,
                                        uint32_t a2, uint32_t a3,
                                        uint32_t b0, uint32_t b1) {
    asm volatile(
        "mma.sync.aligned.m16n8k16.row.col.f32.f16.f16.f32 "
        "{%0,%1,%2,%3}, {%4,%5,%6,%7}, {%8,%9}, {%0,%1,%2,%3};"
        : "+f"(c[0]), "+f"(c[1]), "+f"(c[2]), "+f"(c[3])
        : "r"(a0), "r"(a1), "r"(a2), "r"(a3), "r"(b0), "r"(b1));
}

// ---------------- weight pre-split (input + output weights) -----------------
__global__ void k_wsplit(const float* __restrict__ W_in,
                         const float* __restrict__ W_out,
                         uint32_t* __restrict__ wph, uint32_t* __restrict__ wpl,
                         uint32_t* __restrict__ woh, uint32_t* __restrict__ wol) {
    int i = blockIdx.x * blockDim.x + threadIdx.x;
    float v0, v1;
    uint32_t *ph, *pl;
    int idx;
    if (i < PIN) {
        int k2 = i / 128, n = i % 128;
        v0 = W_in[(2 * k2) * 128 + n];
        v1 = W_in[(2 * k2 + 1) * 128 + n];
        ph = wph; pl = wpl; idx = i;
    } else if (i < PIN + POUT) {
        int j = i - PIN;
        int k2 = j / 40, n = j % 40;
        v0 = W_out[(2 * k2) * 40 + n];
        v1 = W_out[(2 * k2 + 1) * 40 + n];
        ph = woh; pl = wol; idx = j;
    } else return;
    __half h0 = __float2half_rn(v0), h1 = __float2half_rn(v1);
    float l0 = v0 - __half2float(h0), l1 = v1 - __half2float(h1);
    __half2 hh = __halves2half2(h0, h1);
    ph[idx] = *(uint32_t*)&hh;
    pl[idx] = pack2(l0, l1);
}

#define LDP 136
#define LDA32 40   // A-pair stride for 32-row prod tiles (40 mod 32 == 8)

// ---------------- multi-block fp32 128x128x128 product (3-pass HMMA) --------
// grid (4, njobs): block b computes rows [32b, 32b+32) of O = A @ B.
struct PJob { const float* A; const float* B; float* O; };
struct PBatch { PJob j[3]; };

__global__ __launch_bounds__(256) void k_prod(PBatch batch)
{
    const PJob jb = batch.j[blockIdx.y];

    __shared__ uint32_t Ah[8 * LDA32], Al[8 * LDA32];
    __shared__ uint32_t Bh[8 * LDP],   Bl[8 * LDP];

    const int tid  = threadIdx.x;
    const int wid  = tid >> 5;
    const int lane = tid & 31;
    const int g    = lane >> 2;
    const int tg   = lane & 3;
    const int wm   = (wid & 1) * 16;    // 2 m-tiles of 16
    const int wn   = (wid >> 1) * 32;   // 4 n-groups of 32
    const int brow = blockIdx.x * 32;

    const int bk2 = tid >> 5;           // 0..7
    const int bn4 = (tid & 31) * 4;

    float acc[4][4];
#pragma unroll
    for (int nt = 0; nt < 4; nt++)
#pragma unroll
        for (int j = 0; j < 4; j++) acc[nt][j] = 0.0f;

    for (int t = 0; t < 8; t++) {
        // A tile 32x16 fp32 -> split pairs [k2][m], 128 threads x 1 float4
        if (tid < 128) {
            int r  = tid >> 2;
            int c4 = (tid & 3) * 4;
            float4 av = *(const float4*)&jb.A[(size_t)(brow + r) * 128 + t * 16 + c4];
            float aa[4] = {av.x, av.y, av.z, av.w};
            int k2 = c4 >> 1;
            __half h0 = __float2half_rn(aa[0]), h1 = __float2half_rn(aa[1]);
            __half h2 = __float2half_rn(aa[2]), h3 = __float2half_rn(aa[3]);
            __half2 p01 = __halves2half2(h0, h1), p23 = __halves2half2(h2, h3);
            Ah[(k2 + 0) * LDA32 + r] = *(uint32_t*)&p01;
            Ah[(k2 + 1) * LDA32 + r] = *(uint32_t*)&p23;
            Al[(k2 + 0) * LDA32 + r] =
                pack2(aa[0] - __half2float(h0), aa[1] - __half2float(h1));
            Al[(k2 + 1) * LDA32 + r] =
                pack2(aa[2] - __half2float(h2), aa[3] - __half2float(h3));
        }
        // B tile 16x128 fp32 -> split pairs [k2][n]
        {
            const float* r0 = &jb.B[(size_t)(t * 16 + 2 * bk2) * 128 + bn4];
            const float* r1 = r0 + 128;
            float4 bv0 = *(const float4*)r0;
            float4 bv1 = *(const float4*)r1;
            float e0[4] = {bv0.x, bv0.y, bv0.z, bv0.w};
            float e1[4] = {bv1.x, bv1.y, bv1.z, bv1.w};
#pragma unroll
            for (int j = 0; j < 4; j++) {
                __half h0 = __float2half_rn(e0[j]), h1 = __float2half_rn(e1[j]);
                __half2 hp = __halves2half2(h0, h1);
                Bh[bk2 * LDP + bn4 + j] = *(uint32_t*)&hp;
                Bl[bk2 * LDP + bn4 + j] =
                    pack2(e0[j] - __half2float(h0), e1[j] - __half2float(h1));
            }
        }
        __syncthreads();

        uint32_t a0h = Ah[tg * LDA32 + wm + g];
        uint32_t a1h = Ah[tg * LDA32 + wm + g + 8];
        uint32_t a2h = Ah[(tg + 4) * LDA32 + wm + g];
        uint32_t a3h = Ah[(tg + 4) * LDA32 + wm + g + 8];
        uint32_t a0l = Al[tg * LDA32 + wm + g];
        uint32_t a1l = Al[tg * LDA32 + wm + g + 8];
        uint32_t a2l = Al[(tg + 4) * LDA32 + wm + g];
        uint32_t a3l = Al[(tg + 4) * LDA32 + wm + g + 8];
#pragma unroll
        for (int nt = 0; nt < 4; nt++) {
            int n0 = wn + nt * 8;
            uint32_t b0h = Bh[tg * LDP + n0 + g];
            uint32_t b1h = Bh[(tg + 4) * LDP + n0 + g];
            uint32_t b0l = Bl[tg * LDP + n0 + g];
            uint32_t b1l = Bl[(tg + 4) * LDP + n0 + g];
            mma_f16(acc[nt], a0h, a1h, a2h, a3h, b0h, b1h);
            mma_f16(acc[nt], a0l, a1l, a2l, a3l, b0h, b1h);
            mma_f16(acc[nt], a0h, a1h, a2h, a3h, b0l, b1l);
        }
        __syncthreads();
    }

    int r0 = brow + wm + g;
    int r1 = r0 + 8;
#pragma unroll
    for (int nt = 0; nt < 4; nt++) {
        int col = wn + nt * 8 + tg * 2;
        *(float2*)&jb.O[(size_t)r0 * 128 + col] = make_float2(acc[nt][0], acc[nt][1]);
        *(float2*)&jb.O[(size_t)r1 * 128 + col] = make_float2(acc[nt][2], acc[nt][3]);
    }
}

// ---------------- pack chain-product weights to split-fp16 pairs ------------
__global__ void k_pack(const float* __restrict__ W_gcn,
                       const float* __restrict__ S,
                       uint32_t* __restrict__ wch, uint32_t* __restrict__ wcl) {
    int i = blockIdx.x * blockDim.x + threadIdx.x;
    if (i >= 4 * PC) return;
    int c = i / PC, p = i % PC;
    int k2 = p / 128, n = p % 128;
    const float* M;
    switch (c) {
        case 0: M = W_gcn;          break;   // chain 1: W0
        case 1: M = S + 0 * 16384;  break;   // chain 2: S2
        case 2: M = S + 2 * 16384;  break;   // chain 3: S345
        default: M = S + 5 * 16384; break;   // chain 4: S6789
    }
    float v0 = M[(2 * k2) * 128 + n];
    float v1 = M[(2 * k2 + 1) * 128 + n];
    __half h0 = __float2half_rn(v0), h1 = __float2half_rn(v1);
    __half2 hh = __halves2half2(h0, h1);
    wch[i] = *(uint32_t*)&hh;
    wcl[i] = pack2(v0 - __half2float(h0), v1 - __half2float(h1));
}

// ---------------- correction vectors ----------------------------------------
// base pass: zero all slots; t==0 slots = bias of chain's last layer
__global__ void k_cvec(const float* __restrict__ b_gcn, float* __restrict__ C) {
    int i = blockIdx.x * blockDim.x + threadIdx.x;
    if (i >= 16 * 128) return;
    int slot = i >> 7, n = i & 127;
    int c = slot >> 2, t = slot & 3;
    float v = 0.0f;
    if (t == 0) {
        const int last[4] = {0, 2, 5, 9};
        v = b_gcn[last[c] * HH + n];
    }
    C[i] = v;
}

// matrix-multiplied correction terms (6 jobs x 128 cols)
__global__ void k_cvec2(const float* __restrict__ W_gcn,
                        const float* __restrict__ b_gcn,
                        const float* __restrict__ S,
                        float* __restrict__ C) {
    int job = blockIdx.x;
    int n = threadIdx.x;
    if (n >= 128) return;
    const float* bias;
    const float* M;
    int slot;
    switch (job) {
        case 0: bias = b_gcn + 1 * HH; M = W_gcn + 2 * HH * HH; slot = 1 * 4 + 1; break; // b1*W2
        case 1: bias = b_gcn + 4 * HH; M = W_gcn + 5 * HH * HH; slot = 2 * 4 + 1; break; // b4*W5
        case 2: bias = b_gcn + 3 * HH; M = S + 1 * 16384;       slot = 2 * 4 + 2; break; // b3*S45
        case 3: bias = b_gcn + 8 * HH; M = W_gcn + 9 * HH * HH; slot = 3 * 4 + 1; break; // b8*W9
        case 4: bias = b_gcn + 7 * HH; M = S + 3 * 16384;       slot = 3 * 4 + 2; break; // b7*S89
        default: bias = b_gcn + 6 * HH; M = S + 4 * 16384;      slot = 3 * 4 + 3; break; // b6*S789
    }
    float s = 0.0f;
#pragma unroll 8
    for (int k = 0; k < 128; k++) s += bias[k] * M[k * 128 + n];
    C[slot * 128 + n] = s;
}

// ---------------- degree / CSR build ----------------------------------------
__global__ void k_deg_init(float* __restrict__ deg, int* __restrict__ cnt,
                           float* __restrict__ R) {
    int i = blockIdx.x * blockDim.x + threadIdx.x;
    if (i < NN) { deg[i] = 1.0f; cnt[i] = 0; R[i * 4] = 1.0f; }
}

__global__ void k_deg_acc(const int* __restrict__ ei, const float* __restrict__ ew,
                          float* __restrict__ deg, int* __restrict__ cnt) {
    int e = blockIdx.x * blockDim.x + threadIdx.x;
    if (e < EE) {
        int d = ei[EE + e];
        atomicAdd(&deg[d], ew[e]);
        atomicAdd(&cnt[d], 1);
    }
}

__global__ void k_scan1(const int* __restrict__ cnt, int* __restrict__ bsum) {
    __shared__ int s[256];
    int i = blockIdx.x * 256 + threadIdx.x;
    s[threadIdx.x] = (i < NN) ? cnt[i] : 0;
    __syncthreads();
    for (int off = 128; off > 0; off >>= 1) {
        if (threadIdx.x < off) s[threadIdx.x] += s[threadIdx.x + off];
        __syncthreads();
    }
    if (threadIdx.x == 0) bsum[blockIdx.x] = s[0];
}

__global__ void k_scan2(const int* __restrict__ bsum, int* __restrict__ boff,
                        int* __restrict__ rowptr) {
    __shared__ int s[256];
    int t = threadIdx.x;
    int v = (t < NB_SCAN) ? bsum[t] : 0;
    s[t] = v;
    __syncthreads();
    for (int off = 1; off < 256; off <<= 1) {
        int u = (t >= off) ? s[t - off] : 0;
        __syncthreads();
        s[t] += u;
        __syncthreads();
    }
    boff[t] = s[t] - v;
    if (t == 255) rowptr[NN] = s[255];
}

__global__ void k_scan3(const int* __restrict__ cnt, const int* __restrict__ boff,
                        int* __restrict__ rowptr, int* __restrict__ cursor) {
    __shared__ int s[256];
    int i = blockIdx.x * 256 + threadIdx.x;
    int t = threadIdx.x;
    int v = (i < NN) ? cnt[i] : 0;
    s[t] = v;
    __syncthreads();
    for (int off = 1; off < 256; off <<= 1) {
        int u = (t >= off) ? s[t - off] : 0;
        __syncthreads();
        s[t] += u;
        __syncthreads();
    }
    int ex = boff[blockIdx.x] + s[t] - v;
    if (i < NN) { rowptr[i] = ex; cursor[i] = ex; }
}

__global__ void k_fill(const int* __restrict__ ei, const float* __restrict__ ew,
                       const float* __restrict__ deg, int* __restrict__ cursor,
                       int2* __restrict__ edge) {
    int e = blockIdx.x * blockDim.x + threadIdx.x;
    if (e < EE) {
        int s = ei[e], d = ei[EE + e];
        int pos = atomicAdd(&cursor[d], 1);
        float w = ew[e] * rsqrtf(deg[s]) * rsqrtf(deg[d]);
        edge[pos] = make_int2(s, __float_as_int(w));
    }
}

// ---------------- r vectors: R[:,t] = A_norm * R[:,t-1] ---------------------
__global__ void k_rvec(const int* __restrict__ rowptr, const int2* __restrict__ edge,
                       const float* __restrict__ deg, float* __restrict__ R, int t) {
    int d = blockIdx.x * blockDim.x + threadIdx.x;
    if (d >= NN) return;
    float acc = R[d * 4 + t - 1] / deg[d];
    int e  = rowptr[d];
    int e1 = rowptr[d + 1];
    for (; e < e1; e++) {
        int2 p = __ldg(&edge[e]);
        acc += __int_as_float(p.y) * R[p.x * 4 + t - 1];
    }
    R[d * 4 + t] = acc;
}

// ---------------- input GEMM: fp32 A split to fp16 hi/lo, 3-pass HMMA -------
__global__ __launch_bounds__(256) void k_mma_in(
    const float* __restrict__ A,
    const uint32_t* __restrict__ Bh_g, const uint32_t* __restrict__ Bl_g,
    const float* __restrict__ bias, __half* __restrict__ catH)
{
    __shared__ uint32_t Ah[8 * LDP], Al[8 * LDP];
    __shared__ uint32_t Bh[8 * LDP], Bl[8 * LDP];

    const int tid  = threadIdx.x;
    const int wid  = tid >> 5;
    const int lane = tid & 31;
    const int g    = lane >> 2;
    const int tg   = lane & 3;
    const int wm   = (wid & 3) * 32;
    const int wn   = (wid >> 2) * 64;
    const int brow = blockIdx.x * 128;

    int ar[2], ac[2];
#pragma unroll
    for (int l = 0; l < 2; l++) {
        int v = tid + l * 256;
        ar[l] = v >> 2;  ac[l] = (v & 3) * 4;
    }
    const int brr = tid >> 5;
    const int bcc = (tid & 31) * 4;

    float acc[2][8][4];
#pragma unroll
    for (int mt = 0; mt < 2; mt++)
#pragma unroll
        for (int nt = 0; nt < 8; nt++)
#pragma unroll
            for (int j = 0; j < 4; j++) acc[mt][nt][j] = 0.0f;

    const int nt_tiles = FF / 16;

    float4 pa[2];
    uint4  pbh, pbl;

    auto fetch = [&](int t) {
#pragma unroll
        for (int l = 0; l < 2; l++) {
            int grow = brow + ar[l];
            pa[l] = make_float4(0.f, 0.f, 0.f, 0.f);
            if (grow < NN)
                pa[l] = *(const float4*)&A[(size_t)grow * FF + t * 16 + ac[l]];
        }
        pbh = *(const uint4*)&Bh_g[(size_t)(t * 8 + brr) * 128 + bcc];
        pbl = *(const uint4*)&Bl_g[(size_t)(t * 8 + brr) * 128 + bcc];
    };
    auto store = [&]() {
#pragma unroll
        for (int l = 0; l < 2; l++) {
            float fx = pa[l].x, fy = pa[l].y, fz = pa[l].z, fw = pa[l].w;
            __half hx = __float2half_rn(fx), hy = __float2half_rn(fy);
            __half hz = __float2half_rn(fz), hw_ = __float2half_rn(fw);
            __half2 h01 = __halves2half2(hx, hy), h23 = __halves2half2(hz, hw_);
            int k2 = ac[l] >> 1;
            Ah[(k2 + 0) * LDP + ar[l]] = *(uint32_t*)&h01;
            Ah[(k2 + 1) * LDP + ar[l]] = *(uint32_t*)&h23;
            Al[(k2 + 0) * LDP + ar[l]] =
                pack2(fx - __half2float(hx), fy - __half2float(hy));
            Al[(k2 + 1) * LDP + ar[l]] =
                pack2(fz - __half2float(hz), fw - __half2float(hw_));
        }
        *(uint4*)&Bh[brr * LDP + bcc] = pbh;
        *(uint4*)&Bl[brr * LDP + bcc] = pbl;
    };

    fetch(0);
    store();
    __syncthreads();

    for (int t = 0; t < nt_tiles; t++) {
        if (t + 1 < nt_tiles) fetch(t + 1);

        uint32_t a0h[2], a1h[2], a2h[2], a3h[2];
        uint32_t a0l[2], a1l[2], a2l[2], a3l[2];
#pragma unroll
        for (int mt = 0; mt < 2; mt++) {
            int m0 = wm + mt * 16;
            a0h[mt] = Ah[tg * LDP + m0 + g];
            a1h[mt] = Ah[tg * LDP + m0 + g + 8];
            a2h[mt] = Ah[(tg + 4) * LDP + m0 + g];
            a3h[mt] = Ah[(tg + 4) * LDP + m0 + g + 8];
            a0l[mt] = Al[tg * LDP + m0 + g];
            a1l[mt] = Al[tg * LDP + m0 + g + 8];
            a2l[mt] = Al[(tg + 4) * LDP + m0 + g];
            a3l[mt] = Al[(tg + 4) * LDP + m0 + g + 8];
        }
#pragma unroll
        for (int nt = 0; nt < 8; nt++) {
            int n0 = wn + nt * 8;
            uint32_t b0h = Bh[tg * LDP + n0 + g];
            uint32_t b1h = Bh[(tg + 4) * LDP + n0 + g];
            uint32_t b0l = Bl[tg * LDP + n0 + g];
            uint32_t b1l = Bl[(tg + 4) * LDP + n0 + g];
#pragma unroll
            for (int mt = 0; mt < 2; mt++) {
                mma_f16(acc[mt][nt], a0h[mt], a1h[mt], a2h[mt], a3h[mt], b0h, b1h);
                mma_f16(acc[mt][nt], a0l[mt], a1l[mt], a2l[mt], a3l[mt], b0h, b1h);
                mma_f16(acc[mt][nt], a0h[mt], a1h[mt], a2h[mt], a3h[mt], b0l, b1l);
            }
        }
        if (t + 1 < nt_tiles) {
            __syncthreads();
            store();
            __syncthreads();
        }
    }

#pragma unroll
    for (int mt = 0; mt < 2; mt++) {
        int r0 = brow + wm + mt * 16 + g;
        int r1 = r0 + 8;
#pragma unroll
        for (int nt = 0; nt < 8; nt++) {
            int col = wn + nt * 8 + tg * 2;
            float b0 = bias[col], b1 = bias[col + 1];
            if (r0 < NN)
                *(__half2*)&catH[(size_t)r0 * NCAT + col] =
                    __floats2half2_rn(acc[mt][nt][0] + b0, acc[mt][nt][1] + b1);
            if (r1 < NN)
                *(__half2*)&catH[(size_t)r1 * NCAT + col] =
                    __floats2half2_rn(acc[mt][nt][2] + b0, acc[mt][nt][3] + b1);
        }
    }
}

// ---------------- chain GEMM with rank-1 correction epilogue ----------------
// dst = A @ Wc + sum_t R[row][t] * C[t][col]
__global__ __launch_bounds__(256) void k_mma_c(
    const __half* __restrict__ A,
    const uint32_t* __restrict__ Bh_g, const uint32_t* __restrict__ Bl_g,
    const float* __restrict__ Cc, const float* __restrict__ R4,
    __half* __restrict__ dst, int ldo)
{
    __shared__ uint32_t As[8 * LDP];
    __shared__ uint32_t Bh[8 * LDP], Bl[8 * LDP];
    __shared__ float Cs[4][128];

    const int tid  = threadIdx.x;
    const int wid  = tid >> 5;
    const int lane = tid & 31;
    const int g    = lane >> 2;
    const int tg   = lane & 3;
    const int wm   = (wid & 3) * 32;
    const int wn   = (wid >> 2) * 64;
    const int brow = blockIdx.x * 128;

    Cs[tid >> 7][(tid & 127)] = Cc[tid];                    // t = 0,1
    Cs[2 + (tid >> 7)][(tid & 127)] = Cc[256 + tid];        // t = 2,3

    const int ar  = tid >> 1;
    const int ak2 = (tid & 1) * 4;
    const int brr = tid >> 5;
    const int bcc = (tid & 31) * 4;

    float acc[2][8][4];
#pragma unroll
    for (int mt = 0; mt < 2; mt++)
#pragma unroll
        for (int nt = 0; nt < 8; nt++)
#pragma unroll
            for (int j = 0; j < 4; j++) acc[mt][nt][j] = 0.0f;

    uint4 pa, pbh, pbl;

    auto fetch = [&](int t) {
        int grow = brow + ar;
        pa = make_uint4(0, 0, 0, 0);
        if (grow < NN)
            pa = *(const uint4*)&A[(size_t)grow * HH + t * 16 + ak2 * 2];
        pbh = *(const uint4*)&Bh_g[(size_t)(t * 8 + brr) * 128 + bcc];
        pbl = *(const uint4*)&Bl_g[(size_t)(t * 8 + brr) * 128 + bcc];
    };
    auto store = [&]() {
        const uint32_t* hp = (const uint32_t*)&pa;
#pragma unroll
        for (int j = 0; j < 4; j++)
            As[(ak2 + j) * LDP + ar] = hp[j];
        *(uint4*)&Bh[brr * LDP + bcc] = pbh;
        *(uint4*)&Bl[brr * LDP + bcc] = pbl;
    };

    fetch(0);
    store();
    __syncthreads();

    for (int t = 0; t < 8; t++) {
        if (t + 1 < 8) fetch(t + 1);

        uint32_t a0[2], a1[2], a2[2], a3[2];
#pragma unroll
        for (int mt = 0; mt < 2; mt++) {
            int m0 = wm + mt * 16;
            a0[mt] = As[tg * LDP + m0 + g];
            a1[mt] = As[tg * LDP + m0 + g + 8];
            a2[mt] = As[(tg + 4) * LDP + m0 + g];
            a3[mt] = As[(tg + 4) * LDP + m0 + g + 8];
        }
#pragma unroll
        for (int nt = 0; nt < 8; nt++) {
            int n0 = wn + nt * 8;
            uint32_t b0h = Bh[tg * LDP + n0 + g];
            uint32_t b1h = Bh[(tg + 4) * LDP + n0 + g];
            uint32_t b0l = Bl[tg * LDP + n0 + g];
            uint32_t b1l = Bl[(tg + 4) * LDP + n0 + g];
#pragma unroll
            for (int mt = 0; mt < 2; mt++) {
                mma_f16(acc[mt][nt], a0[mt], a1[mt], a2[mt], a3[mt], b0h, b1h);
                mma_f16(acc[mt][nt], a0[mt], a1[mt], a2[mt], a3[mt], b0l, b1l);
            }
        }
        if (t + 1 < 8) {
            __syncthreads();
            store();
            __syncthreads();
        }
    }

#pragma unroll
    for (int mt = 0; mt < 2; mt++) {
        int r0 = brow + wm + mt * 16 + g;
        int r1 = r0 + 8;
        float4 rv0 = make_float4(0.f, 0.f, 0.f, 0.f);
        float4 rv1 = rv0;
        if (r0 < NN) rv0 = *(const float4*)&R4[(size_t)r0 * 4];
        if (r1 < NN) rv1 = *(const float4*)&R4[(size_t)r1 * 4];
#pragma unroll
        for (int nt = 0; nt < 8; nt++) {
            int col = wn + nt * 8 + tg * 2;
            float c00 = Cs[0][col],     c10 = Cs[1][col];
            float c20 = Cs[2][col],     c30 = Cs[3][col];
            float c01 = Cs[0][col + 1], c11 = Cs[1][col + 1];
            float c21 = Cs[2][col + 1], c31 = Cs[3][col + 1];
            if (r0 < NN) {
                float e0 = rv0.x * c00 + rv0.y * c10 + rv0.z * c20 + rv0.w * c30;
                float e1 = rv0.x * c01 + rv0.y * c11 + rv0.z * c21 + rv0.w * c31;
                *(__half2*)&dst[(size_t)r0 * ldo + col] =
                    __floats2half2_rn(acc[mt][nt][0] + e0, acc[mt][nt][1] + e1);
            }
            if (r1 < NN) {
                float e0 = rv1.x * c00 + rv1.y * c10 + rv1.z * c20 + rv1.w * c30;
                float e1 = rv1.x * c01 + rv1.y * c11 + rv1.z * c21 + rv1.w * c31;
                *(__half2*)&dst[(size_t)r1 * ldo + col] =
                    __floats2half2_rn(acc[mt][nt][2] + e0, acc[mt][nt][3] + e1);
            }
        }
    }
}

// ---------------- CSR aggregation: out = A_norm * in (fp16) -----------------
__global__ __launch_bounds__(256) void k_aggr(
    const int* __restrict__ rowptr, const int2* __restrict__ edge,
    const float* __restrict__ deg, const __half* __restrict__ Hin, int lda,
    __half* __restrict__ out)
{
    int node = (blockIdx.x * blockDim.x + threadIdx.x) >> 5;
    if (node >= NN) return;
    int lane = threadIdx.x & 31;

    const uint2* mh = (const uint2*)Hin;
    const int ld2 = lda >> 2;

    auto loadf4 = [&](int n) -> float4 {
        uint2 p = __ldg(&mh[(size_t)n * ld2 + lane]);
        __half2 h0 = *(__half2*)&p.x;
        __half2 h1 = *(__half2*)&p.y;
        float2 f0 = __half22float2(h0);
        float2 f1 = __half22float2(h1);
        return make_float4(f0.x, f0.y, f1.x, f1.y);
    };

    float sn = 1.0f / deg[node];
    float4 self = loadf4(node);
    float4 acc;
    acc.x = self.x * sn;
    acc.y = self.y * sn;
    acc.z = self.z * sn;
    acc.w = self.w * sn;

    int e  = rowptr[node];
    int e1 = rowptr[node + 1];
    for (; e + 3 < e1; e += 4) {
        int2 p0 = __ldg(&edge[e]),     p1 = __ldg(&edge[e + 1]);
        int2 p2 = __ldg(&edge[e + 2]), p3 = __ldg(&edge[e + 3]);
        float w0 = __int_as_float(p0.y), w1 = __int_as_float(p1.y);
        float w2 = __int_as_float(p2.y), w3 = __int_as_float(p3.y);
        float4 v0 = loadf4(p0.x), v1 = loadf4(p1.x);
        float4 v2 = loadf4(p2.x), v3 = loadf4(p3.x);
        acc.x += w0 * v0.x + w1 * v1.x + w2 * v2.x + w3 * v3.x;
        acc.y += w0 * v0.y + w1 * v1.y + w2 * v2.y + w3 * v3.y;
        acc.z += w0 * v0.z + w1 * v1.z + w2 * v2.z + w3 * v3.z;
        acc.w += w0 * v0.w + w1 * v1.w + w2 * v2.w + w3 * v3.w;
    }
    for (; e < e1; e++) {
        int2 p0 = __ldg(&edge[e]);
        float w0 = __int_as_float(p0.y);
        float4 v0 = loadf4(p0.x);
        acc.x += w0 * v0.x;
        acc.y += w0 * v0.y;
        acc.z += w0 * v0.z;
        acc.w += w0 * v0.w;
    }

    union { uint2 u; __half2 h[2]; } pk;
    pk.h[0] = __floats2half2_rn(acc.x, acc.y);
    pk.h[1] = __floats2half2_rn(acc.z, acc.w);
    *(uint2*)&out[(size_t)node * HH + lane * 4] = pk.u;
}

// ---------------- final: out = cat16 @ W_out + b_out (2-pass HMMA) ----------
#define LDA2 264

__global__ __launch_bounds__(256) void k_out(
    const __half* __restrict__ cat,
    const uint32_t* __restrict__ Woh, const uint32_t* __restrict__ Wol,
    const float* __restrict__ b, float* __restrict__ out)
{
    __shared__ uint32_t As[8 * LDA2];
    __shared__ uint32_t Bh[8 * 40], Bl[8 * 40];

    const int tid  = threadIdx.x;
    const int wid  = tid >> 5;
    const int lane = tid & 31;
    const int g    = lane >> 2;
    const int tg   = lane & 3;
    const int wm   = wid * 32;
    const int brow = blockIdx.x * 256;

    float acc[2][5][4];
#pragma unroll
    for (int mt = 0; mt < 2; mt++)
#pragma unroll
        for (int nt = 0; nt < 5; nt++)
#pragma unroll
            for (int j = 0; j < 4; j++) acc[mt][nt][j] = 0.0f;

    for (int t = 0; t < NCAT / 16; t++) {
#pragma unroll
        for (int l = 0; l < 2; l++) {
            int v   = tid + l * 256;
            int r   = v >> 1;
            int k2  = (v & 1) * 4;
            int grow = brow + r;
            uint4 av = make_uint4(0, 0, 0, 0);
            if (grow < NN)
                av = *(const uint4*)&cat[(size_t)grow * NCAT + t * 16 + k2 * 2];
            const uint32_t* hp = (const uint32_t*)&av;
#pragma unroll
            for (int j = 0; j < 4; j++)
                As[(k2 + j) * LDA2 + r] = hp[j];
        }
        for (int idx = tid; idx < 8 * 40; idx += 256) {
            Bh[idx] = Woh[t * 320 + idx];
            Bl[idx] = Wol[t * 320 + idx];
        }
        __syncthreads();

        uint32_t a0[2], a1[2], a2[2], a3[2];
#pragma unroll
        for (int mt = 0; mt < 2; mt++) {
            int m0 = wm + mt * 16;
            a0[mt] = As[tg * LDA2 + m0 + g];
            a1[mt] = As[tg * LDA2 + m0 + g + 8];
            a2[mt] = As[(tg + 4) * LDA2 + m0 + g];
            a3[mt] = As[(tg + 4) * LDA2 + m0 + g + 8];
        }
#pragma unroll
        for (int nt = 0; nt < 5; nt++) {
            int n0 = nt * 8;
            uint32_t b0h = Bh[tg * 40 + n0 + g];
            uint32_t b1h = Bh[(tg + 4) * 40 + n0 + g];
            uint32_t b0l = Bl[tg * 40 + n0 + g];
            uint32_t b1l = Bl[(tg + 4) * 40 + n0 + g];
#pragma unroll
            for (int mt = 0; mt < 2; mt++) {
                mma_f16(acc[mt][nt], a0[mt], a1[mt], a2[mt], a3[mt], b0h, b1h);
                mma_f16(acc[mt][nt], a0[mt], a1[mt], a2[mt], a3[mt], b0l, b1l);
            }
        }
        __syncthreads();
    }

#pragma unroll
    for (int mt = 0; mt < 2; mt++) {
        int r0 = brow + wm + mt * 16 + g;
        int r1 = r0 + 8;
#pragma unroll
        for (int nt = 0; nt < 5; nt++) {
            int col = nt * 8 + tg * 2;
            float b0 = b[col], b1 = b[col + 1];
            if (r0 < NN) {
                float2 v = make_float2(acc[mt][nt][0] + b0, acc[mt][nt][1] + b1);
                *(float2*)&out[(size_t)r0 * CC + col] = v;
            }
            if (r1 < NN) {
                float2 v = make_float2(acc[mt][nt][2] + b0, acc[mt][nt][3] + b1);
                *(float2*)&out[(size_t)r1 * CC + col] = v;
            }
        }
    }
}

// ---------------- streams / events (created once) ----------------------------
struct GraphCtx {
    cudaStream_t s2;
    cudaEvent_t  e_root, e_w;
    GraphCtx() {
        cudaFree(0);
        cudaStreamCreateWithFlags(&s2, cudaStreamNonBlocking);
        cudaEventCreateWithFlags(&e_root, cudaEventDisableTiming);
        cudaEventCreateWithFlags(&e_w,    cudaEventDisableTiming);
    }
};
static GraphCtx g_ctx;

// ---------------- launch ------------------------------------------------------
extern "C" void kernel_launch(void* const* d_in, const int* in_sizes, int n_in,
                              void* d_out, int out_size) {
    const float* x     = (const float*)d_in[0];
    const int*   ei    = (const int*)  d_in[1];
    const float* ew    = (const float*)d_in[2];
    const float* W_in  = (const float*)d_in[3];
    const float* b_in  = (const float*)d_in[4];
    const float* W_gcn = (const float*)d_in[5];
    const float* b_gcn = (const float*)d_in[6];
    const float* W_out = (const float*)d_in[7];
    const float* b_out = (const float*)d_in[8];
    float* out = (float*)d_out;

    float *deg, *S, *C, *R;
    __half *ah1, *ah2, *ah3, *ah4, *cat;
    uint32_t *wph, *wpl, *woh, *wol, *wch, *wcl;
    int *cnt, *rowptr, *cursor, *bsum, *boff;
    int2* edge;
    cudaGetSymbolAddress((void**)&deg,    g_deg);
    cudaGetSymbolAddress((void**)&ah1,    g_ah1);
    cudaGetSymbolAddress((void**)&ah2,    g_ah2);
    cudaGetSymbolAddress((void**)&ah3,    g_ah3);
    cudaGetSymbolAddress((void**)&ah4,    g_ah4);
    cudaGetSymbolAddress((void**)&cat,    g_cat);
    cudaGetSymbolAddress((void**)&wph,    g_wph);
    cudaGetSymbolAddress((void**)&wpl,    g_wpl);
    cudaGetSymbolAddress((void**)&woh,    g_woh);
    cudaGetSymbolAddress((void**)&wol,    g_wol);
    cudaGetSymbolAddress((void**)&wch,    g_wch);
    cudaGetSymbolAddress((void**)&wcl,    g_wcl);
    cudaGetSymbolAddress((void**)&S,      g_S);
    cudaGetSymbolAddress((void**)&C,      g_C);
    cudaGetSymbolAddress((void**)&R,      g_R);
    cudaGetSymbolAddress((void**)&cnt,    g_cnt);
    cudaGetSymbolAddress((void**)&rowptr, g_rowptr);
    cudaGetSymbolAddress((void**)&cursor, g_cursor);
    cudaGetSymbolAddress((void**)&edge,   g_edge);
    cudaGetSymbolAddress((void**)&bsum,   g_bsum);
    cudaGetSymbolAddress((void**)&boff,   g_boff);

    const int gb = (NN + 127) / 128;
    const int ga = (NN * 32 + 255) / 256;
    const float* Wg = W_gcn;

    cudaStream_t sM = 0;          // capture-origin stream
    cudaStream_t s2 = g_ctx.s2;

    // fork
    cudaEventRecord(g_ctx.e_root, sM);
    cudaStreamWaitEvent(s2, g_ctx.e_root, 0);

    // --- s2: weight precompute chain + input GEMM ---
    k_wsplit<<<(PIN + POUT + 255) / 256, 256, 0, s2>>>(W_in, W_out,
                                                       wph, wpl, woh, wol);
    {   // step 1: S2 = W1*W2 ; S45 = W4*W5 ; S89 = W8*W9
        PBatch pb;
        pb.j[0] = {Wg + 1 * 16384, Wg + 2 * 16384, S + 0 * 16384};
        pb.j[1] = {Wg + 4 * 16384, Wg + 5 * 16384, S + 1 * 16384};
        pb.j[2] = {Wg + 8 * 16384, Wg + 9 * 16384, S + 3 * 16384};
        k_prod<<<dim3(4, 3), 256, 0, s2>>>(pb);
    }
    {   // step 2: S345 = W3*S45 ; S789 = W7*S89
        PBatch pb;
        pb.j[0] = {Wg + 3 * 16384, S + 1 * 16384, S + 2 * 16384};
        pb.j[1] = {Wg + 7 * 16384, S + 3 * 16384, S + 4 * 16384};
        pb.j[2] = pb.j[0];
        k_prod<<<dim3(4, 2), 256, 0, s2>>>(pb);
    }
    {   // step 3: S6789 = W6*S789
        PBatch pb;
        pb.j[0] = {Wg + 6 * 16384, S + 4 * 16384, S + 5 * 16384};
        pb.j[1] = pb.j[0]; pb.j[2] = pb.j[0];
        k_prod<<<dim3(4, 1), 256, 0, s2>>>(pb);
    }
    k_pack  <<<(4 * PC + 255) / 256, 256, 0, s2>>>(Wg, S, wch, wcl);
    k_cvec  <<<(16 * 128 + 255) / 256, 256, 0, s2>>>(b_gcn, C);
    k_cvec2 <<<6, 128, 0, s2>>>(Wg, b_gcn, S, C);
    k_mma_in<<<gb, 256, 0, s2>>>(x, wph, wpl, b_in, cat);   // h -> cat[:,0:128]
    cudaEventRecord(g_ctx.e_w, s2);

    // --- main: CSR + degree + r-vectors (overlapped with s2) ---
    k_deg_init<<<(NN + 255) / 256, 256, 0, sM>>>(deg, cnt, R);
    k_deg_acc <<<(EE + 255) / 256, 256, 0, sM>>>(ei, ew, deg, cnt);
    k_scan1   <<<NB_SCAN, 256, 0, sM>>>(cnt, bsum);
    k_scan2   <<<1, 256, 0, sM>>>(bsum, boff, rowptr);
    k_scan3   <<<NB_SCAN, 256, 0, sM>>>(cnt, boff, rowptr, cursor);
    k_fill    <<<(EE + 255) / 256, 256, 0, sM>>>(ei, ew, deg, cursor, edge);
    k_rvec    <<<NB_SCAN, 256, 0, sM>>>(rowptr, edge, deg, R, 1);
    k_rvec    <<<NB_SCAN, 256, 0, sM>>>(rowptr, edge, deg, R, 2);
    k_rvec    <<<NB_SCAN, 256, 0, sM>>>(rowptr, edge, deg, R, 3);

    // join
    cudaStreamWaitEvent(sM, g_ctx.e_w, 0);

    // power sequence + chain GEMMs (interleaved for L2 locality)
    k_aggr <<<ga, 256, 0, sM>>>(rowptr, edge, deg, cat, NCAT, ah1);
    k_mma_c<<<gb, 256, 0, sM>>>(ah1, wch + 0 * PC, wcl + 0 * PC, C + 0 * 512, R,
                                cat + 1 * HH, NCAT);
    k_aggr <<<ga, 256, 0, sM>>>(rowptr, edge, deg, ah1, HH, ah2);
    k_mma_c<<<gb, 256, 0, sM>>>(ah2, wch + 1 * PC, wcl + 1 * PC, C + 1 * 512, R,
                                cat + 2 * HH, NCAT);
    k_aggr <<<ga, 256, 0, sM>>>(rowptr, edge, deg, ah2, HH, ah3);
    k_mma_c<<<gb, 256, 0, sM>>>(ah3, wch + 2 * PC, wcl + 2 * PC, C + 2 * 512, R,
                                cat + 3 * HH, NCAT);
    k_aggr <<<ga, 256, 0, sM>>>(rowptr, edge, deg, ah3, HH, ah4);
    k_mma_c<<<gb, 256, 0, sM>>>(ah4, wch + 3 * PC, wcl + 3 * PC, C + 3 * 512, R,
                                cat + 4 * HH, NCAT);

    // out = cat @ W_out + b_out
    k_out<<<(NN + 255) / 256, 256, 0, sM>>>(cat, woh, wol, b_out, out);
}

// round 15
// speedup vs baseline: 1.5513x; 1.0926x over previous
#include <cuda_runtime.h>
#include <cuda_fp16.h>
#include <cstdint>

#define NN 50000
#define EE 800000
#define FF 512
#define HH 128
#define CC 40
#define NCAT 640     // (1 + 4) * 128
#define NB_SCAN 196  // ceil(NN / 256)

#define PIN   (256 * 128)     // input weights:  512x128 -> 256x128 pairs
#define POUT  (320 * 40)      // out weights: 640x40 -> 320x40 pairs
#define PC    8192            // one chain product: 64x128 pairs

// ---------------- scratch (device globals; no allocation allowed) -----------
static __device__ __align__(256) float    g_deg[NN];
static __device__ __align__(256) __half   g_ah1[NN * HH];  // A^1 h .. A^4 h
static __device__ __align__(256) __half   g_ah2[NN * HH];
static __device__ __align__(256) __half   g_ah3[NN * HH];
static __device__ __align__(256) __half   g_ah4[NN * HH];
static __device__ __align__(256) __half   g_cat[(size_t)NN * NCAT];
// split-fp16 packed weights
static __device__ __align__(256) uint32_t g_wph[PIN],  g_wpl[PIN];    // input
static __device__ __align__(256) uint32_t g_woh[POUT], g_wol[POUT];   // out
static __device__ __align__(256) uint32_t g_wch[4 * PC], g_wcl[4 * PC]; // chain prods
// fp32 weight-product scratch: 0:S2 1:S45 2:S345 3:S89 4:S789 5:S6789 6:W67
static __device__ __align__(256) float    g_S[7 * 16384];
static __device__ __align__(256) float    g_C[16 * 128];   // corrections [chain][t][n]
static __device__ __align__(256) float    g_R[NN * 4];     // (1, r1, r2, r3) per node
// CSR scratch
static __device__ __align__(256) int   g_cnt[NN];
static __device__ __align__(256) int   g_rowptr[NN + 1];
static __device__ __align__(256) int   g_cursor[NN];
static __device__ __align__(256) int2  g_edge[EE];         // {src, w-as-int}
static __device__ __align__(256) int   g_bsum[256];
static __device__ __align__(256) int   g_boff[256];

__device__ __forceinline__ uint32_t pack2(float a, float b) {
    __half2 h = __floats2half2_rn(a, b);
    return *(uint32_t*)&h;
}

__device__ __forceinline__ void mma_f16(float c[4], uint32_t a0, uint32_t a1,
                                        uint32_t a2, uint32_t a3,
                                        uint32_t b0, uint32_t b1) {
    asm volatile(
        "mma.sync.aligned.m16n8k16.row.col.f32.f16.f16.f32 "
        "{%0,%1,%2,%3}, {%4,%5,%6,%7}, {%8,%9}, {%0,%1,%2,%3};"
        : "+f"(c[0]), "+f"(c[1]), "+f"(c[2]), "+f"(c[3])
        : "r"(a0), "r"(a1), "r"(a2), "r"(a3), "r"(b0), "r"(b1));
}

// ---------------- weight pre-split (input + output weights) -----------------
__global__ void k_wsplit(const float* __restrict__ W_in,
                         const float* __restrict__ W_out,
                         uint32_t* __restrict__ wph, uint32_t* __restrict__ wpl,
                         uint32_t* __restrict__ woh, uint32_t* __restrict__ wol) {
    int i = blockIdx.x * blockDim.x + threadIdx.x;
    float v0, v1;
    uint32_t *ph, *pl;
    int idx;
    if (i < PIN) {
        int k2 = i / 128, n = i % 128;
        v0 = W_in[(2 * k2) * 128 + n];
        v1 = W_in[(2 * k2 + 1) * 128 + n];
        ph = wph; pl = wpl; idx = i;
    } else if (i < PIN + POUT) {
        int j = i - PIN;
        int k2 = j / 40, n = j % 40;
        v0 = W_out[(2 * k2) * 40 + n];
        v1 = W_out[(2 * k2 + 1) * 40 + n];
        ph = woh; pl = wol; idx = j;
    } else return;
    __half h0 = __float2half_rn(v0), h1 = __float2half_rn(v1);
    float l0 = v0 - __half2float(h0), l1 = v1 - __half2float(h1);
    __half2 hh = __halves2half2(h0, h1);
    ph[idx] = *(uint32_t*)&hh;
    pl[idx] = pack2(l0, l1);
}

#define LDP 136
#define LDA32 40   // A-pair stride for 32-row prod tiles (40 mod 32 == 8)

// ---------------- multi-block fp32 128x128x128 product (3-pass HMMA) --------
// grid (4, njobs): block b computes rows [32b, 32b+32) of O = A @ B.
struct PJob { const float* A; const float* B; float* O; };
struct PBatch { PJob j[4]; };

__global__ __launch_bounds__(256) void k_prod(PBatch batch)
{
    const PJob jb = batch.j[blockIdx.y];

    __shared__ uint32_t Ah[8 * LDA32], Al[8 * LDA32];
    __shared__ uint32_t Bh[8 * LDP],   Bl[8 * LDP];

    const int tid  = threadIdx.x;
    const int wid  = tid >> 5;
    const int lane = tid & 31;
    const int g    = lane >> 2;
    const int tg   = lane & 3;
    const int wm   = (wid & 1) * 16;    // 2 m-tiles of 16
    const int wn   = (wid >> 1) * 32;   // 4 n-groups of 32
    const int brow = blockIdx.x * 32;

    const int bk2 = tid >> 5;           // 0..7
    const int bn4 = (tid & 31) * 4;

    float acc[4][4];
#pragma unroll
    for (int nt = 0; nt < 4; nt++)
#pragma unroll
        for (int j = 0; j < 4; j++) acc[nt][j] = 0.0f;

    for (int t = 0; t < 8; t++) {
        // A tile 32x16 fp32 -> split pairs [k2][m], 128 threads x 1 float4
        if (tid < 128) {
            int r  = tid >> 2;
            int c4 = (tid & 3) * 4;
            float4 av = *(const float4*)&jb.A[(size_t)(brow + r) * 128 + t * 16 + c4];
            float aa[4] = {av.x, av.y, av.z, av.w};
            int k2 = c4 >> 1;
            __half h0 = __float2half_rn(aa[0]), h1 = __float2half_rn(aa[1]);
            __half h2 = __float2half_rn(aa[2]), h3 = __float2half_rn(aa[3]);
            __half2 p01 = __halves2half2(h0, h1), p23 = __halves2half2(h2, h3);
            Ah[(k2 + 0) * LDA32 + r] = *(uint32_t*)&p01;
            Ah[(k2 + 1) * LDA32 + r] = *(uint32_t*)&p23;
            Al[(k2 + 0) * LDA32 + r] =
                pack2(aa[0] - __half2float(h0), aa[1] - __half2float(h1));
            Al[(k2 + 1) * LDA32 + r] =
                pack2(aa[2] - __half2float(h2), aa[3] - __half2float(h3));
        }
        // B tile 16x128 fp32 -> split pairs [k2][n]
        {
            const float* r0 = &jb.B[(size_t)(t * 16 + 2 * bk2) * 128 + bn4];
            const float* r1 = r0 + 128;
            float4 bv0 = *(const float4*)r0;
            float4 bv1 = *(const float4*)r1;
            float e0[4] = {bv0.x, bv0.y, bv0.z, bv0.w};
            float e1[4] = {bv1.x, bv1.y, bv1.z, bv1.w};
#pragma unroll
            for (int j = 0; j < 4; j++) {
                __half h0 = __float2half_rn(e0[j]), h1 = __float2half_rn(e1[j]);
                __half2 hp = __halves2half2(h0, h1);
                Bh[bk2 * LDP + bn4 + j] = *(uint32_t*)&hp;
                Bl[bk2 * LDP + bn4 + j] =
                    pack2(e0[j] - __half2float(h0), e1[j] - __half2float(h1));
            }
        }
        __syncthreads();

        uint32_t a0h = Ah[tg * LDA32 + wm + g];
        uint32_t a1h = Ah[tg * LDA32 + wm + g + 8];
        uint32_t a2h = Ah[(tg + 4) * LDA32 + wm + g];
        uint32_t a3h = Ah[(tg + 4) * LDA32 + wm + g + 8];
        uint32_t a0l = Al[tg * LDA32 + wm + g];
        uint32_t a1l = Al[tg * LDA32 + wm + g + 8];
        uint32_t a2l = Al[(tg + 4) * LDA32 + wm + g];
        uint32_t a3l = Al[(tg + 4) * LDA32 + wm + g + 8];
#pragma unroll
        for (int nt = 0; nt < 4; nt++) {
            int n0 = wn + nt * 8;
            uint32_t b0h = Bh[tg * LDP + n0 + g];
            uint32_t b1h = Bh[(tg + 4) * LDP + n0 + g];
            uint32_t b0l = Bl[tg * LDP + n0 + g];
            uint32_t b1l = Bl[(tg + 4) * LDP + n0 + g];
            mma_f16(acc[nt], a0h, a1h, a2h, a3h, b0h, b1h);
            mma_f16(acc[nt], a0l, a1l, a2l, a3l, b0h, b1h);
            mma_f16(acc[nt], a0h, a1h, a2h, a3h, b0l, b1l);
        }
        __syncthreads();
    }

    int r0 = brow + wm + g;
    int r1 = r0 + 8;
#pragma unroll
    for (int nt = 0; nt < 4; nt++) {
        int col = wn + nt * 8 + tg * 2;
        *(float2*)&jb.O[(size_t)r0 * 128 + col] = make_float2(acc[nt][0], acc[nt][1]);
        *(float2*)&jb.O[(size_t)r1 * 128 + col] = make_float2(acc[nt][2], acc[nt][3]);
    }
}

// ---------------- pack chain-product weights to split-fp16 pairs ------------
__global__ void k_pack(const float* __restrict__ W_gcn,
                       const float* __restrict__ S,
                       uint32_t* __restrict__ wch, uint32_t* __restrict__ wcl) {
    int i = blockIdx.x * blockDim.x + threadIdx.x;
    if (i >= 4 * PC) return;
    int c = i / PC, p = i % PC;
    int k2 = p / 128, n = p % 128;
    const float* M;
    switch (c) {
        case 0: M = W_gcn;          break;   // chain 1: W0
        case 1: M = S + 0 * 16384;  break;   // chain 2: S2
        case 2: M = S + 2 * 16384;  break;   // chain 3: S345
        default: M = S + 5 * 16384; break;   // chain 4: S6789
    }
    float v0 = M[(2 * k2) * 128 + n];
    float v1 = M[(2 * k2 + 1) * 128 + n];
    __half h0 = __float2half_rn(v0), h1 = __float2half_rn(v1);
    __half2 hh = __halves2half2(h0, h1);
    wch[i] = *(uint32_t*)&hh;
    wcl[i] = pack2(v0 - __half2float(h0), v1 - __half2float(h1));
}

// ---------------- correction vectors ----------------------------------------
// base pass: zero all slots; t==0 slots = bias of chain's last layer
__global__ void k_cvec(const float* __restrict__ b_gcn, float* __restrict__ C) {
    int i = blockIdx.x * blockDim.x + threadIdx.x;
    if (i >= 16 * 128) return;
    int slot = i >> 7, n = i & 127;
    int c = slot >> 2, t = slot & 3;
    float v = 0.0f;
    if (t == 0) {
        const int last[4] = {0, 2, 5, 9};
        v = b_gcn[last[c] * HH + n];
    }
    C[i] = v;
}

// matrix-multiplied correction terms (6 jobs x 128 cols)
__global__ void k_cvec2(const float* __restrict__ W_gcn,
                        const float* __restrict__ b_gcn,
                        const float* __restrict__ S,
                        float* __restrict__ C) {
    int job = blockIdx.x;
    int n = threadIdx.x;
    if (n >= 128) return;
    const float* bias;
    const float* M;
    int slot;
    switch (job) {
        case 0: bias = b_gcn + 1 * HH; M = W_gcn + 2 * HH * HH; slot = 1 * 4 + 1; break; // b1*W2
        case 1: bias = b_gcn + 4 * HH; M = W_gcn + 5 * HH * HH; slot = 2 * 4 + 1; break; // b4*W5
        case 2: bias = b_gcn + 3 * HH; M = S + 1 * 16384;       slot = 2 * 4 + 2; break; // b3*S45
        case 3: bias = b_gcn + 8 * HH; M = W_gcn + 9 * HH * HH; slot = 3 * 4 + 1; break; // b8*W9
        case 4: bias = b_gcn + 7 * HH; M = S + 3 * 16384;       slot = 3 * 4 + 2; break; // b7*S89
        default: bias = b_gcn + 6 * HH; M = S + 4 * 16384;      slot = 3 * 4 + 3; break; // b6*S789
    }
    float s = 0.0f;
#pragma unroll 8
    for (int k = 0; k < 128; k++) s += bias[k] * M[k * 128 + n];
    C[slot * 128 + n] = s;
}

// ---------------- degree / CSR build ----------------------------------------
__global__ void k_deg_init(float* __restrict__ deg, int* __restrict__ cnt,
                           float* __restrict__ R) {
    int i = blockIdx.x * blockDim.x + threadIdx.x;
    if (i < NN) { deg[i] = 1.0f; cnt[i] = 0; R[i * 4] = 1.0f; }
}

__global__ void k_deg_acc(const int* __restrict__ ei, const float* __restrict__ ew,
                          float* __restrict__ deg, int* __restrict__ cnt) {
    int e = blockIdx.x * blockDim.x + threadIdx.x;
    if (e < EE) {
        int d = ei[EE + e];
        atomicAdd(&deg[d], ew[e]);
        atomicAdd(&cnt[d], 1);
    }
}

__global__ void k_scan1(const int* __restrict__ cnt, int* __restrict__ bsum) {
    __shared__ int s[256];
    int i = blockIdx.x * 256 + threadIdx.x;
    s[threadIdx.x] = (i < NN) ? cnt[i] : 0;
    __syncthreads();
    for (int off = 128; off > 0; off >>= 1) {
        if (threadIdx.x < off) s[threadIdx.x] += s[threadIdx.x + off];
        __syncthreads();
    }
    if (threadIdx.x == 0) bsum[blockIdx.x] = s[0];
}

__global__ void k_scan2(const int* __restrict__ bsum, int* __restrict__ boff,
                        int* __restrict__ rowptr) {
    __shared__ int s[256];
    int t = threadIdx.x;
    int v = (t < NB_SCAN) ? bsum[t] : 0;
    s[t] = v;
    __syncthreads();
    for (int off = 1; off < 256; off <<= 1) {
        int u = (t >= off) ? s[t - off] : 0;
        __syncthreads();
        s[t] += u;
        __syncthreads();
    }
    boff[t] = s[t] - v;
    if (t == 255) rowptr[NN] = s[255];
}

__global__ void k_scan3(const int* __restrict__ cnt, const int* __restrict__ boff,
                        int* __restrict__ rowptr, int* __restrict__ cursor) {
    __shared__ int s[256];
    int i = blockIdx.x * 256 + threadIdx.x;
    int t = threadIdx.x;
    int v = (i < NN) ? cnt[i] : 0;
    s[t] = v;
    __syncthreads();
    for (int off = 1; off < 256; off <<= 1) {
        int u = (t >= off) ? s[t - off] : 0;
        __syncthreads();
        s[t] += u;
        __syncthreads();
    }
    int ex = boff[blockIdx.x] + s[t] - v;
    if (i < NN) { rowptr[i] = ex; cursor[i] = ex; }
}

__global__ void k_fill(const int* __restrict__ ei, const float* __restrict__ ew,
                       const float* __restrict__ deg, int* __restrict__ cursor,
                       int2* __restrict__ edge) {
    int e = blockIdx.x * blockDim.x + threadIdx.x;
    if (e < EE) {
        int s = ei[e], d = ei[EE + e];
        int pos = atomicAdd(&cursor[d], 1);
        float w = ew[e] * rsqrtf(deg[s]) * rsqrtf(deg[d]);
        edge[pos] = make_int2(s, __float_as_int(w));
    }
}

// ---------------- r vectors: R[:,t] = A_norm * R[:,t-1] ---------------------
__global__ void k_rvec(const int* __restrict__ rowptr, const int2* __restrict__ edge,
                       const float* __restrict__ deg, float* __restrict__ R, int t) {
    int d = blockIdx.x * blockDim.x + threadIdx.x;
    if (d >= NN) return;
    float acc = R[d * 4 + t - 1] / deg[d];
    int e  = rowptr[d];
    int e1 = rowptr[d + 1];
    for (; e < e1; e++) {
        int2 p = __ldg(&edge[e]);
        acc += __int_as_float(p.y) * R[p.x * 4 + t - 1];
    }
    R[d * 4 + t] = acc;
}

// ---------------- input GEMM: fp32 A split to fp16 hi/lo, 3-pass HMMA -------
__global__ __launch_bounds__(256) void k_mma_in(
    const float* __restrict__ A,
    const uint32_t* __restrict__ Bh_g, const uint32_t* __restrict__ Bl_g,
    const float* __restrict__ bias, __half* __restrict__ catH)
{
    __shared__ uint32_t Ah[8 * LDP], Al[8 * LDP];
    __shared__ uint32_t Bh[8 * LDP], Bl[8 * LDP];

    const int tid  = threadIdx.x;
    const int wid  = tid >> 5;
    const int lane = tid & 31;
    const int g    = lane >> 2;
    const int tg   = lane & 3;
    const int wm   = (wid & 3) * 32;
    const int wn   = (wid >> 2) * 64;
    const int brow = blockIdx.x * 128;

    int ar[2], ac[2];
#pragma unroll
    for (int l = 0; l < 2; l++) {
        int v = tid + l * 256;
        ar[l] = v >> 2;  ac[l] = (v & 3) * 4;
    }
    const int brr = tid >> 5;
    const int bcc = (tid & 31) * 4;

    float acc[2][8][4];
#pragma unroll
    for (int mt = 0; mt < 2; mt++)
#pragma unroll
        for (int nt = 0; nt < 8; nt++)
#pragma unroll
            for (int j = 0; j < 4; j++) acc[mt][nt][j] = 0.0f;

    const int nt_tiles = FF / 16;

    float4 pa[2];
    uint4  pbh, pbl;

    auto fetch = [&](int t) {
#pragma unroll
        for (int l = 0; l < 2; l++) {
            int grow = brow + ar[l];
            pa[l] = make_float4(0.f, 0.f, 0.f, 0.f);
            if (grow < NN)
                pa[l] = *(const float4*)&A[(size_t)grow * FF + t * 16 + ac[l]];
        }
        pbh = *(const uint4*)&Bh_g[(size_t)(t * 8 + brr) * 128 + bcc];
        pbl = *(const uint4*)&Bl_g[(size_t)(t * 8 + brr) * 128 + bcc];
    };
    auto store = [&]() {
#pragma unroll
        for (int l = 0; l < 2; l++) {
            float fx = pa[l].x, fy = pa[l].y, fz = pa[l].z, fw = pa[l].w;
            __half hx = __float2half_rn(fx), hy = __float2half_rn(fy);
            __half hz = __float2half_rn(fz), hw_ = __float2half_rn(fw);
            __half2 h01 = __halves2half2(hx, hy), h23 = __halves2half2(hz, hw_);
            int k2 = ac[l] >> 1;
            Ah[(k2 + 0) * LDP + ar[l]] = *(uint32_t*)&h01;
            Ah[(k2 + 1) * LDP + ar[l]] = *(uint32_t*)&h23;
            Al[(k2 + 0) * LDP + ar[l]] =
                pack2(fx - __half2float(hx), fy - __half2float(hy));
            Al[(k2 + 1) * LDP + ar[l]] =
                pack2(fz - __half2float(hz), fw - __half2float(hw_));
        }
        *(uint4*)&Bh[brr * LDP + bcc] = pbh;
        *(uint4*)&Bl[brr * LDP + bcc] = pbl;
    };

    fetch(0);
    store();
    __syncthreads();

    for (int t = 0; t < nt_tiles; t++) {
        if (t + 1 < nt_tiles) fetch(t + 1);

        uint32_t a0h[2], a1h[2], a2h[2], a3h[2];
        uint32_t a0l[2], a1l[2], a2l[2], a3l[2];
#pragma unroll
        for (int mt = 0; mt < 2; mt++) {
            int m0 = wm + mt * 16;
            a0h[mt] = Ah[tg * LDP + m0 + g];
            a1h[mt] = Ah[tg * LDP + m0 + g + 8];
            a2h[mt] = Ah[(tg + 4) * LDP + m0 + g];
            a3h[mt] = Ah[(tg + 4) * LDP + m0 + g + 8];
            a0l[mt] = Al[tg * LDP + m0 + g];
            a1l[mt] = Al[tg * LDP + m0 + g + 8];
            a2l[mt] = Al[(tg + 4) * LDP + m0 + g];
            a3l[mt] = Al[(tg + 4) * LDP + m0 + g + 8];
        }
#pragma unroll
        for (int nt = 0; nt < 8; nt++) {
            int n0 = wn + nt * 8;
            uint32_t b0h = Bh[tg * LDP + n0 + g];
            uint32_t b1h = Bh[(tg + 4) * LDP + n0 + g];
            uint32_t b0l = Bl[tg * LDP + n0 + g];
            uint32_t b1l = Bl[(tg + 4) * LDP + n0 + g];
#pragma unroll
            for (int mt = 0; mt < 2; mt++) {
                mma_f16(acc[mt][nt], a0h[mt], a1h[mt], a2h[mt], a3h[mt], b0h, b1h);
                mma_f16(acc[mt][nt], a0l[mt], a1l[mt], a2l[mt], a3l[mt], b0h, b1h);
                mma_f16(acc[mt][nt], a0h[mt], a1h[mt], a2h[mt], a3h[mt], b0l, b1l);
            }
        }
        if (t + 1 < nt_tiles) {
            __syncthreads();
            store();
            __syncthreads();
        }
    }

#pragma unroll
    for (int mt = 0; mt < 2; mt++) {
        int r0 = brow + wm + mt * 16 + g;
        int r1 = r0 + 8;
#pragma unroll
        for (int nt = 0; nt < 8; nt++) {
            int col = wn + nt * 8 + tg * 2;
            float b0 = bias[col], b1 = bias[col + 1];
            if (r0 < NN)
                *(__half2*)&catH[(size_t)r0 * NCAT + col] =
                    __floats2half2_rn(acc[mt][nt][0] + b0, acc[mt][nt][1] + b1);
            if (r1 < NN)
                *(__half2*)&catH[(size_t)r1 * NCAT + col] =
                    __floats2half2_rn(acc[mt][nt][2] + b0, acc[mt][nt][3] + b1);
        }
    }
}

// ---------------- chain GEMM with rank-1 correction epilogue ----------------
// dst = A @ Wc + sum_t R[row][t] * C[t][col]
__global__ __launch_bounds__(256) void k_mma_c(
    const __half* __restrict__ A,
    const uint32_t* __restrict__ Bh_g, const uint32_t* __restrict__ Bl_g,
    const float* __restrict__ Cc, const float* __restrict__ R4,
    __half* __restrict__ dst, int ldo)
{
    __shared__ uint32_t As[8 * LDP];
    __shared__ uint32_t Bh[8 * LDP], Bl[8 * LDP];
    __shared__ float Cs[4][128];

    const int tid  = threadIdx.x;
    const int wid  = tid >> 5;
    const int lane = tid & 31;
    const int g    = lane >> 2;
    const int tg   = lane & 3;
    const int wm   = (wid & 3) * 32;
    const int wn   = (wid >> 2) * 64;
    const int brow = blockIdx.x * 128;

    Cs[tid >> 7][(tid & 127)] = Cc[tid];                    // t = 0,1
    Cs[2 + (tid >> 7)][(tid & 127)] = Cc[256 + tid];        // t = 2,3

    const int ar  = tid >> 1;
    const int ak2 = (tid & 1) * 4;
    const int brr = tid >> 5;
    const int bcc = (tid & 31) * 4;

    float acc[2][8][4];
#pragma unroll
    for (int mt = 0; mt < 2; mt++)
#pragma unroll
        for (int nt = 0; nt < 8; nt++)
#pragma unroll
            for (int j = 0; j < 4; j++) acc[mt][nt][j] = 0.0f;

    uint4 pa, pbh, pbl;

    auto fetch = [&](int t) {
        int grow = brow + ar;
        pa = make_uint4(0, 0, 0, 0);
        if (grow < NN)
            pa = *(const uint4*)&A[(size_t)grow * HH + t * 16 + ak2 * 2];
        pbh = *(const uint4*)&Bh_g[(size_t)(t * 8 + brr) * 128 + bcc];
        pbl = *(const uint4*)&Bl_g[(size_t)(t * 8 + brr) * 128 + bcc];
    };
    auto store = [&]() {
        const uint32_t* hp = (const uint32_t*)&pa;
#pragma unroll
        for (int j = 0; j < 4; j++)
            As[(ak2 + j) * LDP + ar] = hp[j];
        *(uint4*)&Bh[brr * LDP + bcc] = pbh;
        *(uint4*)&Bl[brr * LDP + bcc] = pbl;
    };

    fetch(0);
    store();
    __syncthreads();

    for (int t = 0; t < 8; t++) {
        if (t + 1 < 8) fetch(t + 1);

        uint32_t a0[2], a1[2], a2[2], a3[2];
#pragma unroll
        for (int mt = 0; mt < 2; mt++) {
            int m0 = wm + mt * 16;
            a0[mt] = As[tg * LDP + m0 + g];
            a1[mt] = As[tg * LDP + m0 + g + 8];
            a2[mt] = As[(tg + 4) * LDP + m0 + g];
            a3[mt] = As[(tg + 4) * LDP + m0 + g + 8];
        }
#pragma unroll
        for (int nt = 0; nt < 8; nt++) {
            int n0 = wn + nt * 8;
            uint32_t b0h = Bh[tg * LDP + n0 + g];
            uint32_t b1h = Bh[(tg + 4) * LDP + n0 + g];
            uint32_t b0l = Bl[tg * LDP + n0 + g];
            uint32_t b1l = Bl[(tg + 4) * LDP + n0 + g];
#pragma unroll
            for (int mt = 0; mt < 2; mt++) {
                mma_f16(acc[mt][nt], a0[mt], a1[mt], a2[mt], a3[mt], b0h, b1h);
                mma_f16(acc[mt][nt], a0[mt], a1[mt], a2[mt], a3[mt], b0l, b1l);
            }
        }
        if (t + 1 < 8) {
            __syncthreads();
            store();
            __syncthreads();
        }
    }

#pragma unroll
    for (int mt = 0; mt < 2; mt++) {
        int r0 = brow + wm + mt * 16 + g;
        int r1 = r0 + 8;
        float4 rv0 = make_float4(0.f, 0.f, 0.f, 0.f);
        float4 rv1 = rv0;
        if (r0 < NN) rv0 = *(const float4*)&R4[(size_t)r0 * 4];
        if (r1 < NN) rv1 = *(const float4*)&R4[(size_t)r1 * 4];
#pragma unroll
        for (int nt = 0; nt < 8; nt++) {
            int col = wn + nt * 8 + tg * 2;
            float c00 = Cs[0][col],     c10 = Cs[1][col];
            float c20 = Cs[2][col],     c30 = Cs[3][col];
            float c01 = Cs[0][col + 1], c11 = Cs[1][col + 1];
            float c21 = Cs[2][col + 1], c31 = Cs[3][col + 1];
            if (r0 < NN) {
                float e0 = rv0.x * c00 + rv0.y * c10 + rv0.z * c20 + rv0.w * c30;
                float e1 = rv0.x * c01 + rv0.y * c11 + rv0.z * c21 + rv0.w * c31;
                *(__half2*)&dst[(size_t)r0 * ldo + col] =
                    __floats2half2_rn(acc[mt][nt][0] + e0, acc[mt][nt][1] + e1);
            }
            if (r1 < NN) {
                float e0 = rv1.x * c00 + rv1.y * c10 + rv1.z * c20 + rv1.w * c30;
                float e1 = rv1.x * c01 + rv1.y * c11 + rv1.z * c21 + rv1.w * c31;
                *(__half2*)&dst[(size_t)r1 * ldo + col] =
                    __floats2half2_rn(acc[mt][nt][2] + e0, acc[mt][nt][3] + e1);
            }
        }
    }
}

// ---------------- CSR aggregation: out = A_norm * in (fp16) -----------------
__global__ __launch_bounds__(256) void k_aggr(
    const int* __restrict__ rowptr, const int2* __restrict__ edge,
    const float* __restrict__ deg, const __half* __restrict__ Hin, int lda,
    __half* __restrict__ out)
{
    int node = (blockIdx.x * blockDim.x + threadIdx.x) >> 5;
    if (node >= NN) return;
    int lane = threadIdx.x & 31;

    const uint2* mh = (const uint2*)Hin;
    const int ld2 = lda >> 2;

    auto loadf4 = [&](int n) -> float4 {
        uint2 p = __ldg(&mh[(size_t)n * ld2 + lane]);
        __half2 h0 = *(__half2*)&p.x;
        __half2 h1 = *(__half2*)&p.y;
        float2 f0 = __half22float2(h0);
        float2 f1 = __half22float2(h1);
        return make_float4(f0.x, f0.y, f1.x, f1.y);
    };

    float sn = 1.0f / deg[node];
    float4 self = loadf4(node);
    float4 acc;
    acc.x = self.x * sn;
    acc.y = self.y * sn;
    acc.z = self.z * sn;
    acc.w = self.w * sn;

    int e  = rowptr[node];
    int e1 = rowptr[node + 1];
    for (; e + 3 < e1; e += 4) {
        int2 p0 = __ldg(&edge[e]),     p1 = __ldg(&edge[e + 1]);
        int2 p2 = __ldg(&edge[e + 2]), p3 = __ldg(&edge[e + 3]);
        float w0 = __int_as_float(p0.y), w1 = __int_as_float(p1.y);
        float w2 = __int_as_float(p2.y), w3 = __int_as_float(p3.y);
        float4 v0 = loadf4(p0.x), v1 = loadf4(p1.x);
        float4 v2 = loadf4(p2.x), v3 = loadf4(p3.x);
        acc.x += w0 * v0.x + w1 * v1.x + w2 * v2.x + w3 * v3.x;
        acc.y += w0 * v0.y + w1 * v1.y + w2 * v2.y + w3 * v3.y;
        acc.z += w0 * v0.z + w1 * v1.z + w2 * v2.z + w3 * v3.z;
        acc.w += w0 * v0.w + w1 * v1.w + w2 * v2.w + w3 * v3.w;
    }
    for (; e < e1; e++) {
        int2 p0 = __ldg(&edge[e]);
        float w0 = __int_as_float(p0.y);
        float4 v0 = loadf4(p0.x);
        acc.x += w0 * v0.x;
        acc.y += w0 * v0.y;
        acc.z += w0 * v0.z;
        acc.w += w0 * v0.w;
    }

    union { uint2 u; __half2 h[2]; } pk;
    pk.h[0] = __floats2half2_rn(acc.x, acc.y);
    pk.h[1] = __floats2half2_rn(acc.z, acc.w);
    *(uint2*)&out[(size_t)node * HH + lane * 4] = pk.u;
}

// ---------------- final: out = cat16 @ W_out + b_out (2-pass HMMA) ----------
#define LDA2 264

__global__ __launch_bounds__(256) void k_out(
    const __half* __restrict__ cat,
    const uint32_t* __restrict__ Woh, const uint32_t* __restrict__ Wol,
    const float* __restrict__ b, float* __restrict__ out)
{
    __shared__ uint32_t As[8 * LDA2];
    __shared__ uint32_t Bh[8 * 40], Bl[8 * 40];

    const int tid  = threadIdx.x;
    const int wid  = tid >> 5;
    const int lane = tid & 31;
    const int g    = lane >> 2;
    const int tg   = lane & 3;
    const int wm   = wid * 32;
    const int brow = blockIdx.x * 256;

    float acc[2][5][4];
#pragma unroll
    for (int mt = 0; mt < 2; mt++)
#pragma unroll
        for (int nt = 0; nt < 5; nt++)
#pragma unroll
            for (int j = 0; j < 4; j++) acc[mt][nt][j] = 0.0f;

    for (int t = 0; t < NCAT / 16; t++) {
#pragma unroll
        for (int l = 0; l < 2; l++) {
            int v   = tid + l * 256;
            int r   = v >> 1;
            int k2  = (v & 1) * 4;
            int grow = brow + r;
            uint4 av = make_uint4(0, 0, 0, 0);
            if (grow < NN)
                av = *(const uint4*)&cat[(size_t)grow * NCAT + t * 16 + k2 * 2];
            const uint32_t* hp = (const uint32_t*)&av;
#pragma unroll
            for (int j = 0; j < 4; j++)
                As[(k2 + j) * LDA2 + r] = hp[j];
        }
        for (int idx = tid; idx < 8 * 40; idx += 256) {
            Bh[idx] = Woh[t * 320 + idx];
            Bl[idx] = Wol[t * 320 + idx];
        }
        __syncthreads();

        uint32_t a0[2], a1[2], a2[2], a3[2];
#pragma unroll
        for (int mt = 0; mt < 2; mt++) {
            int m0 = wm + mt * 16;
            a0[mt] = As[tg * LDA2 + m0 + g];
            a1[mt] = As[tg * LDA2 + m0 + g + 8];
            a2[mt] = As[(tg + 4) * LDA2 + m0 + g];
            a3[mt] = As[(tg + 4) * LDA2 + m0 + g + 8];
        }
#pragma unroll
        for (int nt = 0; nt < 5; nt++) {
            int n0 = nt * 8;
            uint32_t b0h = Bh[tg * 40 + n0 + g];
            uint32_t b1h = Bh[(tg + 4) * 40 + n0 + g];
            uint32_t b0l = Bl[tg * 40 + n0 + g];
            uint32_t b1l = Bl[(tg + 4) * 40 + n0 + g];
#pragma unroll
            for (int mt = 0; mt < 2; mt++) {
                mma_f16(acc[mt][nt], a0[mt], a1[mt], a2[mt], a3[mt], b0h, b1h);
                mma_f16(acc[mt][nt], a0[mt], a1[mt], a2[mt], a3[mt], b0l, b1l);
            }
        }
        __syncthreads();
    }

#pragma unroll
    for (int mt = 0; mt < 2; mt++) {
        int r0 = brow + wm + mt * 16 + g;
        int r1 = r0 + 8;
#pragma unroll
        for (int nt = 0; nt < 5; nt++) {
            int col = nt * 8 + tg * 2;
            float b0 = b[col], b1 = b[col + 1];
            if (r0 < NN) {
                float2 v = make_float2(acc[mt][nt][0] + b0, acc[mt][nt][1] + b1);
                *(float2*)&out[(size_t)r0 * CC + col] = v;
            }
            if (r1 < NN) {
                float2 v = make_float2(acc[mt][nt][2] + b0, acc[mt][nt][3] + b1);
                *(float2*)&out[(size_t)r1 * CC + col] = v;
            }
        }
    }
}

// ---------------- streams / events (created once) ----------------------------
struct GraphCtx {
    cudaStream_t s2;
    cudaEvent_t  e_root, e_w, e_a[4], e_g;
    GraphCtx() {
        cudaFree(0);
        cudaStreamCreateWithFlags(&s2, cudaStreamNonBlocking);
        cudaEventCreateWithFlags(&e_root, cudaEventDisableTiming);
        cudaEventCreateWithFlags(&e_w,    cudaEventDisableTiming);
        for (int i = 0; i < 4; i++)
            cudaEventCreateWithFlags(&e_a[i], cudaEventDisableTiming);
        cudaEventCreateWithFlags(&e_g, cudaEventDisableTiming);
    }
};
static GraphCtx g_ctx;

// ---------------- launch ------------------------------------------------------
extern "C" void kernel_launch(void* const* d_in, const int* in_sizes, int n_in,
                              void* d_out, int out_size) {
    const float* x     = (const float*)d_in[0];
    const int*   ei    = (const int*)  d_in[1];
    const float* ew    = (const float*)d_in[2];
    const float* W_in  = (const float*)d_in[3];
    const float* b_in  = (const float*)d_in[4];
    const float* W_gcn = (const float*)d_in[5];
    const float* b_gcn = (const float*)d_in[6];
    const float* W_out = (const float*)d_in[7];
    const float* b_out = (const float*)d_in[8];
    float* out = (float*)d_out;

    float *deg, *S, *C, *R;
    __half *ah1, *ah2, *ah3, *ah4, *cat;
    uint32_t *wph, *wpl, *woh, *wol, *wch, *wcl;
    int *cnt, *rowptr, *cursor, *bsum, *boff;
    int2* edge;
    cudaGetSymbolAddress((void**)&deg,    g_deg);
    cudaGetSymbolAddress((void**)&ah1,    g_ah1);
    cudaGetSymbolAddress((void**)&ah2,    g_ah2);
    cudaGetSymbolAddress((void**)&ah3,    g_ah3);
    cudaGetSymbolAddress((void**)&ah4,    g_ah4);
    cudaGetSymbolAddress((void**)&cat,    g_cat);
    cudaGetSymbolAddress((void**)&wph,    g_wph);
    cudaGetSymbolAddress((void**)&wpl,    g_wpl);
    cudaGetSymbolAddress((void**)&woh,    g_woh);
    cudaGetSymbolAddress((void**)&wol,    g_wol);
    cudaGetSymbolAddress((void**)&wch,    g_wch);
    cudaGetSymbolAddress((void**)&wcl,    g_wcl);
    cudaGetSymbolAddress((void**)&S,      g_S);
    cudaGetSymbolAddress((void**)&C,      g_C);
    cudaGetSymbolAddress((void**)&R,      g_R);
    cudaGetSymbolAddress((void**)&cnt,    g_cnt);
    cudaGetSymbolAddress((void**)&rowptr, g_rowptr);
    cudaGetSymbolAddress((void**)&cursor, g_cursor);
    cudaGetSymbolAddress((void**)&edge,   g_edge);
    cudaGetSymbolAddress((void**)&bsum,   g_bsum);
    cudaGetSymbolAddress((void**)&boff,   g_boff);

    const int gb = (NN + 127) / 128;
    const int ga = (NN * 32 + 255) / 256;
    const float* Wg = W_gcn;

    cudaStream_t sM = 0;          // capture-origin stream
    cudaStream_t s2 = g_ctx.s2;

    // fork
    cudaEventRecord(g_ctx.e_root, sM);
    cudaStreamWaitEvent(s2, g_ctx.e_root, 0);

    // --- s2: weight precompute chain (depth-2 product tree) + input GEMM ---
    k_wsplit<<<(PIN + POUT + 255) / 256, 256, 0, s2>>>(W_in, W_out,
                                                       wph, wpl, woh, wol);
    {   // step 1: S2=W1*W2 ; S45=W4*W5 ; S89=W8*W9 ; W67=W6*W7
        PBatch pb;
        pb.j[0] = {Wg + 1 * 16384, Wg + 2 * 16384, S + 0 * 16384};
        pb.j[1] = {Wg + 4 * 16384, Wg + 5 * 16384, S + 1 * 16384};
        pb.j[2] = {Wg + 8 * 16384, Wg + 9 * 16384, S + 3 * 16384};
        pb.j[3] = {Wg + 6 * 16384, Wg + 7 * 16384, S + 6 * 16384};
        k_prod<<<dim3(4, 4), 256, 0, s2>>>(pb);
    }
    {   // step 2: S345=W3*S45 ; S789=W7*S89 ; S6789=W67*S89
        PBatch pb;
        pb.j[0] = {Wg + 3 * 16384, S + 1 * 16384, S + 2 * 16384};
        pb.j[1] = {Wg + 7 * 16384, S + 3 * 16384, S + 4 * 16384};
        pb.j[2] = {S + 6 * 16384,  S + 3 * 16384, S + 5 * 16384};
        pb.j[3] = pb.j[0];
        k_prod<<<dim3(4, 3), 256, 0, s2>>>(pb);
    }
    k_pack  <<<(4 * PC + 255) / 256, 256, 0, s2>>>(Wg, S, wch, wcl);
    k_cvec  <<<(16 * 128 + 255) / 256, 256, 0, s2>>>(b_gcn, C);
    k_cvec2 <<<6, 128, 0, s2>>>(Wg, b_gcn, S, C);
    k_mma_in<<<gb, 256, 0, s2>>>(x, wph, wpl, b_in, cat);   // h -> cat[:,0:128]
    cudaEventRecord(g_ctx.e_w, s2);

    // --- main: CSR + degree + r-vectors (overlapped with s2) ---
    k_deg_init<<<(NN + 255) / 256, 256, 0, sM>>>(deg, cnt, R);
    k_deg_acc <<<(EE + 255) / 256, 256, 0, sM>>>(ei, ew, deg, cnt);
    k_scan1   <<<NB_SCAN, 256, 0, sM>>>(cnt, bsum);
    k_scan2   <<<1, 256, 0, sM>>>(bsum, boff, rowptr);
    k_scan3   <<<NB_SCAN, 256, 0, sM>>>(cnt, boff, rowptr, cursor);
    k_fill    <<<(EE + 255) / 256, 256, 0, sM>>>(ei, ew, deg, cursor, edge);
    k_rvec    <<<NB_SCAN, 256, 0, sM>>>(rowptr, edge, deg, R, 1);
    k_rvec    <<<NB_SCAN, 256, 0, sM>>>(rowptr, edge, deg, R, 2);
    k_rvec    <<<NB_SCAN, 256, 0, sM>>>(rowptr, edge, deg, R, 3);

    // join prologues
    cudaStreamWaitEvent(sM, g_ctx.e_w, 0);

    // pipelined mainloop: aggr_{j+1} (sM) overlaps gemm_j (s2);
    // both consumers read the same ah_j buffer (constructive L2 sharing).
    const __half* asrc[5] = {cat, ah1, ah2, ah3, ah4};
    __half* adst[4] = {ah1, ah2, ah3, ah4};
    for (int j = 0; j < 4; j++) {
        k_aggr<<<ga, 256, 0, sM>>>(rowptr, edge, deg, asrc[j],
                                   j == 0 ? NCAT : HH, adst[j]);
        cudaEventRecord(g_ctx.e_a[j], sM);
        cudaStreamWaitEvent(s2, g_ctx.e_a[j], 0);
        k_mma_c<<<gb, 256, 0, s2>>>(adst[j], wch + (size_t)j * PC,
                                    wcl + (size_t)j * PC, C + (size_t)j * 512, R,
                                    cat + (size_t)(j + 1) * HH, NCAT);
    }
    cudaEventRecord(g_ctx.e_g, s2);
    cudaStreamWaitEvent(sM, g_ctx.e_g, 0);

    // out = cat @ W_out + b_out
    k_out<<<(NN + 255) / 256, 256, 0, sM>>>(cat, woh, wol, b_out, out);
}